// round 1
// baseline (speedup 1.0000x reference)
#include <cuda_runtime.h>
#include <math.h>

#define NN 20000
#define CC 32
#define TT 8
#define HH 4
#define FF 256
#define HF 1024
#define EE 320000
#define CT 256
#define BEPS 1e-5f
#define SLOPE 0.2f

// ---------------- scratch (static device globals; no runtime alloc) ----------
__device__ float d_res[NN*CT];
__device__ float d_g1[NN*CT];
__device__ float d_xn[NN*CT];
__device__ float d_h[NN*HF];
__device__ float d_rst[NN*HF];
__device__ float d_el[NN*HH];
__device__ float d_er[NN*HH];
__device__ int   d_counts[NN];
__device__ int   d_rowstart[NN+1];
__device__ int   d_wptr[NN];
__device__ int   d_colsrc[EE];
__device__ float d_bn0sum[64];
__device__ float d_bn1sum[2048];
__device__ float d_bn2sum[64];
__device__ float d_scale[HF];
__device__ float d_shift[HF];

// ---------------- utility ----------------------------------------------------
__global__ void k_zero() {
    int stride = gridDim.x * blockDim.x;
    int i0 = blockIdx.x * blockDim.x + threadIdx.x;
    for (int i = i0; i < NN; i += stride) d_counts[i] = 0;
    for (int i = i0; i < 2048; i += stride) d_bn1sum[i] = 0.f;
    for (int i = i0; i < 64; i += stride) { d_bn0sum[i] = 0.f; d_bn2sum[i] = 0.f; }
}

// stage: 0 -> bn0 (32 ch, M=N*T), 1 -> bn1 (1024 feat, M=N), 2 -> bn2 (32 ch, M=N*T)
__global__ void k_bnfinal(int stage, const float* __restrict__ gamma,
                          const float* __restrict__ beta, float invM) {
    float* sums = (stage == 0) ? d_bn0sum : (stage == 1 ? d_bn1sum : d_bn2sum);
    int nf = (stage == 1) ? 1024 : 32;
    int f = blockIdx.x * blockDim.x + threadIdx.x;
    if (f < nf) {
        float mean = sums[f] * invM;
        float var  = sums[nf + f] * invM - mean * mean;
        float a = gamma[f] * rsqrtf(var + BEPS);
        d_scale[f] = a;
        d_shift[f] = beta[f] - mean * a;
    }
}

// ---------------- front: residual proj + gated_conv1 + bn0 stats -------------
__global__ __launch_bounds__(256) void k_front(
    const float* __restrict__ X,
    const float* __restrict__ rp_w, const float* __restrict__ rp_b,
    const float* __restrict__ w1, const float* __restrict__ b1,
    const float* __restrict__ w2, const float* __restrict__ b2,
    const float* __restrict__ w3, const float* __restrict__ b3)
{
    __shared__ float s_rp[CC*CC];
    __shared__ float s_w1[CC*CC*3];
    __shared__ float s_w2[CC*CC*3];
    __shared__ float s_w3[CC*CC*3];
    __shared__ float s_x[8][CC][TT];

    int tid = threadIdx.x;
    for (int i = tid; i < CC*CC; i += 256) s_rp[i] = rp_w[i];
    for (int i = tid; i < CC*CC*3; i += 256) {
        s_w1[i] = w1[i]; s_w2[i] = w2[i]; s_w3[i] = w3[i];
    }
    int node0 = blockIdx.x * 8;
    for (int i = tid; i < 8*CT; i += 256) {
        int nl = i / CT, r = i % CT;
        int n = node0 + nl;
        s_x[nl][r >> 3][r & 7] = (n < NN) ? X[n*CT + r] : 0.f;
    }
    __syncthreads();

    int c = tid >> 3, t = tid & 7;
    float gv[8];
    float bb1 = b1[c], bb2 = b2[c], bb3 = b3[c], bbr = rp_b[c];
    for (int nl = 0; nl < 8; nl++) {
        int n = node0 + nl;
        float a1 = bb1, a2 = bb2, a3 = bb3, ar = bbr;
        #pragma unroll
        for (int ci = 0; ci < CC; ci++) {
            float x0 = s_x[nl][ci][t];
            float xm = (t > 0) ? s_x[nl][ci][t-1] : 0.f;
            float xp = (t < 7) ? s_x[nl][ci][t+1] : 0.f;
            ar += s_rp[c*CC + ci] * x0;
            int wb = (c*CC + ci) * 3;
            a1 += s_w1[wb]*xm + s_w1[wb+1]*x0 + s_w1[wb+2]*xp;
            a2 += s_w2[wb]*xm + s_w2[wb+1]*x0 + s_w2[wb+2]*xp;
            a3 += s_w3[wb]*xm + s_w3[wb+1]*x0 + s_w3[wb+2]*xp;
        }
        float sig = 1.f / (1.f + expf(-a2));
        float g = a1 * sig + a3;
        g = g > 0.f ? g : 0.f;
        gv[nl] = g;
        if (n < NN) {
            d_res[n*CT + c*TT + t] = ar;
            d_g1 [n*CT + c*TT + t] = g;
        } else gv[nl] = 0.f;
    }
    __syncthreads();
    float* sred = (float*)s_x;
    if (tid < 64) sred[tid] = 0.f;
    __syncthreads();
    float ls = 0.f, lq = 0.f;
    #pragma unroll
    for (int nl = 0; nl < 8; nl++) { ls += gv[nl]; lq += gv[nl]*gv[nl]; }
    atomicAdd(&sred[c], ls);
    atomicAdd(&sred[32 + c], lq);
    __syncthreads();
    if (tid < 32) {
        atomicAdd(&d_bn0sum[tid],      sred[tid]);
        atomicAdd(&d_bn0sum[32 + tid], sred[32 + tid]);
    }
}

// ---------------- apply bn0 -> xn --------------------------------------------
__global__ void k_xn() {
    int i = blockIdx.x * blockDim.x + threadIdx.x;
    if (i < NN*CT) {
        int c = (i & 255) >> 3;
        d_xn[i] = d_g1[i] * d_scale[c] + d_shift[c];
    }
}

// ---------------- GEMM: h = xn @ gat_w^T  (M=20000, K=256, N=1024) ------------
__global__ __launch_bounds__(256) void k_gemm(const float* __restrict__ B) {
    __shared__ float As[8][128];
    __shared__ float Bs[8][128];
    int tid = threadIdx.x;
    int m0 = blockIdx.x * 128, n0 = blockIdx.y * 128;
    int tx = tid & 15, ty = tid >> 4;
    float acc[8][8];
    #pragma unroll
    for (int i = 0; i < 8; i++)
        #pragma unroll
        for (int j = 0; j < 8; j++) acc[i][j] = 0.f;

    int lr = tid >> 1, lk = (tid & 1) * 4;
    for (int k0 = 0; k0 < 256; k0 += 8) {
        int m = m0 + lr;
        float4 av = (m < NN) ? *(const float4*)&d_xn[m*256 + k0 + lk]
                             : make_float4(0.f, 0.f, 0.f, 0.f);
        As[lk+0][lr] = av.x; As[lk+1][lr] = av.y;
        As[lk+2][lr] = av.z; As[lk+3][lr] = av.w;
        float4 bv = *(const float4*)&B[(n0 + lr)*256 + k0 + lk];
        Bs[lk+0][lr] = bv.x; Bs[lk+1][lr] = bv.y;
        Bs[lk+2][lr] = bv.z; Bs[lk+3][lr] = bv.w;
        __syncthreads();
        #pragma unroll
        for (int kk = 0; kk < 8; kk++) {
            float a[8], b[8];
            #pragma unroll
            for (int i = 0; i < 8; i++) a[i] = As[kk][ty*8 + i];
            #pragma unroll
            for (int j = 0; j < 8; j++) b[j] = Bs[kk][tx*8 + j];
            #pragma unroll
            for (int i = 0; i < 8; i++)
                #pragma unroll
                for (int j = 0; j < 8; j++) acc[i][j] += a[i]*b[j];
        }
        __syncthreads();
    }
    #pragma unroll
    for (int i = 0; i < 8; i++) {
        int m = m0 + ty*8 + i;
        if (m < NN) {
            #pragma unroll
            for (int j = 0; j < 8; j++)
                d_h[m*HF + n0 + tx*8 + j] = acc[i][j];
        }
    }
}

// ---------------- el / er -----------------------------------------------------
__global__ __launch_bounds__(128) void k_eler(const float* __restrict__ attn_l,
                                              const float* __restrict__ attn_r) {
    int n = blockIdx.x;
    int w = threadIdx.x >> 5, lane = threadIdx.x & 31;
    const float* hp = &d_h[n*HF + w*FF];
    float sl = 0.f, sr = 0.f;
    #pragma unroll
    for (int f = lane; f < FF; f += 32) {
        float hv = hp[f];
        sl += hv * __ldg(&attn_l[w*FF + f]);
        sr += hv * __ldg(&attn_r[w*FF + f]);
    }
    #pragma unroll
    for (int off = 16; off; off >>= 1) {
        sl += __shfl_down_sync(0xffffffffu, sl, off);
        sr += __shfl_down_sync(0xffffffffu, sr, off);
    }
    if (lane == 0) { d_el[n*HH + w] = sl; d_er[n*HH + w] = sr; }
}

// ---------------- CSR build ---------------------------------------------------
__global__ void k_count(const int* __restrict__ dst) {
    int e = blockIdx.x * blockDim.x + threadIdx.x;
    if (e < EE) atomicAdd(&d_counts[dst[e]], 1);
}

__global__ __launch_bounds__(1024) void k_scan() {
    __shared__ int part[1024];
    int tid = threadIdx.x;
    int beg = tid * 20, end = min(beg + 20, NN);
    int s = 0;
    for (int i = beg; i < end; i++) s += d_counts[i];
    part[tid] = s;
    __syncthreads();
    for (int off = 1; off < 1024; off <<= 1) {
        int v = 0;
        if (tid >= off) v = part[tid - off];
        __syncthreads();
        if (tid >= off) part[tid] += v;
        __syncthreads();
    }
    int run = (tid == 0) ? 0 : part[tid - 1];
    for (int i = beg; i < end; i++) {
        d_rowstart[i] = run; d_wptr[i] = run;
        run += d_counts[i];
    }
    if (tid == 1023) d_rowstart[NN] = run;
}

__global__ void k_fill(const int* __restrict__ src, const int* __restrict__ dst) {
    int e = blockIdx.x * blockDim.x + threadIdx.x;
    if (e < EE) {
        int p = atomicAdd(&d_wptr[dst[e]], 1);
        d_colsrc[p] = src[e];
    }
}

// ---------------- GAT aggregation: warp per dst node --------------------------
__device__ __forceinline__ float lrelu(float x) { return x > 0.f ? x : SLOPE * x; }

__global__ __launch_bounds__(256) void k_agg(const float* __restrict__ bias) {
    int n = (blockIdx.x * blockDim.x + threadIdx.x) >> 5;
    int lane = threadIdx.x & 31;
    if (n >= NN) return;
    int beg = d_rowstart[n], end = d_rowstart[n+1];
    float er0 = d_er[n*4+0], er1 = d_er[n*4+1], er2 = d_er[n*4+2], er3 = d_er[n*4+3];

    float m0 = -1e30f, m1 = -1e30f, m2 = -1e30f, m3 = -1e30f;
    for (int j = beg + lane; j < end; j += 32) {
        int s = d_colsrc[j];
        m0 = fmaxf(m0, lrelu(d_el[s*4+0] + er0));
        m1 = fmaxf(m1, lrelu(d_el[s*4+1] + er1));
        m2 = fmaxf(m2, lrelu(d_el[s*4+2] + er2));
        m3 = fmaxf(m3, lrelu(d_el[s*4+3] + er3));
    }
    #pragma unroll
    for (int off = 16; off; off >>= 1) {
        m0 = fmaxf(m0, __shfl_xor_sync(0xffffffffu, m0, off));
        m1 = fmaxf(m1, __shfl_xor_sync(0xffffffffu, m1, off));
        m2 = fmaxf(m2, __shfl_xor_sync(0xffffffffu, m2, off));
        m3 = fmaxf(m3, __shfl_xor_sync(0xffffffffu, m3, off));
    }
    float s0 = 0.f, s1 = 0.f, s2 = 0.f, s3 = 0.f;
    for (int j = beg + lane; j < end; j += 32) {
        int s = d_colsrc[j];
        s0 += expf(lrelu(d_el[s*4+0] + er0) - m0);
        s1 += expf(lrelu(d_el[s*4+1] + er1) - m1);
        s2 += expf(lrelu(d_el[s*4+2] + er2) - m2);
        s3 += expf(lrelu(d_el[s*4+3] + er3) - m3);
    }
    #pragma unroll
    for (int off = 16; off; off >>= 1) {
        s0 += __shfl_xor_sync(0xffffffffu, s0, off);
        s1 += __shfl_xor_sync(0xffffffffu, s1, off);
        s2 += __shfl_xor_sync(0xffffffffu, s2, off);
        s3 += __shfl_xor_sync(0xffffffffu, s3, off);
    }
    float i0 = s0 > 0.f ? 1.f/s0 : 0.f;
    float i1 = s1 > 0.f ? 1.f/s1 : 0.f;
    float i2 = s2 > 0.f ? 1.f/s2 : 0.f;
    float i3 = s3 > 0.f ? 1.f/s3 : 0.f;

    float acc[32];
    #pragma unroll
    for (int i = 0; i < 32; i++) acc[i] = 0.f;

    for (int j = beg; j < end; j++) {
        int s = d_colsrc[j];
        float w0 = expf(lrelu(d_el[s*4+0] + er0) - m0) * i0;
        float w1 = expf(lrelu(d_el[s*4+1] + er1) - m1) * i1;
        float w2 = expf(lrelu(d_el[s*4+2] + er2) - m2) * i2;
        float w3 = expf(lrelu(d_el[s*4+3] + er3) - m3) * i3;
        const float* hp = &d_h[s*HF + lane];
        #pragma unroll
        for (int i = 0; i < 32; i++) {
            float wv = (i < 8) ? w0 : (i < 16) ? w1 : (i < 24) ? w2 : w3;
            acc[i] += wv * hp[i*32];
        }
    }
    #pragma unroll
    for (int i = 0; i < 32; i++) {
        int f = i*32 + lane;
        float v = acc[i] + __ldg(&bias[f]);
        d_rst[n*HF + f] = v > 0.f ? v : 0.f;
    }
}

// ---------------- bn1 stats (over N, per feature) -----------------------------
__global__ __launch_bounds__(256) void k_bn1stats() {
    int f = blockIdx.x * 256 + threadIdx.x;       // gridDim.x = 4
    int n0 = blockIdx.y * 500;                     // gridDim.y = 40
    float s = 0.f, q = 0.f;
    for (int n = n0; n < n0 + 500; n++) {
        float v = d_rst[n*HF + f];
        s += v; q += v*v;
    }
    atomicAdd(&d_bn1sum[f], s);
    atomicAdd(&d_bn1sum[1024 + f], q);
}

// ---------------- gated_conv2 (+bn1 apply on input, +bn2 stats) ---------------
__global__ __launch_bounds__(256) void k_gated2(
    const float* __restrict__ w1, const float* __restrict__ b1,
    const float* __restrict__ w2, const float* __restrict__ b2,
    const float* __restrict__ w3, const float* __restrict__ b3)
{
    extern __shared__ float sm[];
    float* sw1 = sm;
    float* sw2 = sm + 12288;
    float* sw3 = sm + 24576;
    float* sy  = sm + 36864;   // [8][128][10], time-padded

    int tid = threadIdx.x;
    for (int i = tid; i < 12288; i += 256) {
        sw1[i] = w1[i]; sw2[i] = w2[i]; sw3[i] = w3[i];
    }
    int node0 = blockIdx.x * 8;
    for (int i = tid; i < 8*1024; i += 256) {
        int nl = i >> 10, f = i & 1023;
        int n = node0 + nl;
        float v = (n < NN) ? d_rst[n*HF + f] * d_scale[f] + d_shift[f] : 0.f;
        int ci = f >> 3, t = f & 7;
        sy[(nl*128 + ci)*10 + t + 1] = v;
    }
    for (int i = tid; i < 8*128; i += 256) { sy[i*10] = 0.f; sy[i*10 + 9] = 0.f; }
    __syncthreads();

    int c = tid >> 3, t = tid & 7;
    float a1[8], a2[8], a3[8];
    float bb1 = b1[c], bb2 = b2[c], bb3 = b3[c];
    #pragma unroll
    for (int nl = 0; nl < 8; nl++) { a1[nl] = bb1; a2[nl] = bb2; a3[nl] = bb3; }

    for (int ci = 0; ci < 128; ci++) {
        int wb = (c*128 + ci)*3;
        float w10 = sw1[wb], w11 = sw1[wb+1], w12 = sw1[wb+2];
        float w20 = sw2[wb], w21 = sw2[wb+1], w22 = sw2[wb+2];
        float w30 = sw3[wb], w31 = sw3[wb+1], w32 = sw3[wb+2];
        #pragma unroll
        for (int nl = 0; nl < 8; nl++) {
            const float* xp = &sy[(nl*128 + ci)*10 + t];
            float x0 = xp[0], x1 = xp[1], x2 = xp[2];
            a1[nl] += w10*x0 + w11*x1 + w12*x2;
            a2[nl] += w20*x0 + w21*x1 + w22*x2;
            a3[nl] += w30*x0 + w31*x1 + w32*x2;
        }
    }
    float gv[8];
    #pragma unroll
    for (int nl = 0; nl < 8; nl++) {
        int n = node0 + nl;
        float sig = 1.f / (1.f + expf(-a2[nl]));
        float g = a1[nl]*sig + a3[nl];
        g = g > 0.f ? g : 0.f;
        gv[nl] = g;
        if (n < NN) d_xn[n*CT + c*TT + t] = g;
        else gv[nl] = 0.f;
    }
    __syncthreads();
    float* sred = sm;  // reuse weight region
    if (tid < 64) sred[tid] = 0.f;
    __syncthreads();
    float ls = 0.f, lq = 0.f;
    #pragma unroll
    for (int nl = 0; nl < 8; nl++) { ls += gv[nl]; lq += gv[nl]*gv[nl]; }
    atomicAdd(&sred[c], ls);
    atomicAdd(&sred[32 + c], lq);
    __syncthreads();
    if (tid < 32) {
        atomicAdd(&d_bn2sum[tid],      sred[tid]);
        atomicAdd(&d_bn2sum[32 + tid], sred[32 + tid]);
    }
}

// ---------------- final: bn2 apply + residual + relu --------------------------
__global__ void k_out(float* __restrict__ out) {
    int i = blockIdx.x * blockDim.x + threadIdx.x;
    if (i < NN*CT) {
        int c = (i >> 3) & 31;
        float v = d_xn[i] * d_scale[c] + d_shift[c] + d_res[i];
        out[i] = v > 0.f ? v : 0.f;
    }
}

// ---------------- launch ------------------------------------------------------
extern "C" void kernel_launch(void* const* d_in, const int* in_sizes, int n_in,
                              void* d_out, int out_size) {
    const float* X      = (const float*)d_in[0];
    const int*   src    = (const int*)  d_in[1];
    const int*   dst    = (const int*)  d_in[2];
    const float* rp_w   = (const float*)d_in[3];
    const float* rp_b   = (const float*)d_in[4];
    const float* g1w1   = (const float*)d_in[5];
    const float* g1b1   = (const float*)d_in[6];
    const float* g1w2   = (const float*)d_in[7];
    const float* g1b2   = (const float*)d_in[8];
    const float* g1w3   = (const float*)d_in[9];
    const float* g1b3   = (const float*)d_in[10];
    const float* bn0g   = (const float*)d_in[11];
    const float* bn0b   = (const float*)d_in[12];
    const float* gatw   = (const float*)d_in[13];
    const float* attnl  = (const float*)d_in[14];
    const float* attnr  = (const float*)d_in[15];
    const float* gatb   = (const float*)d_in[16];
    const float* bn1g   = (const float*)d_in[17];
    const float* bn1b   = (const float*)d_in[18];
    const float* g2w1   = (const float*)d_in[19];
    const float* g2b1   = (const float*)d_in[20];
    const float* g2w2   = (const float*)d_in[21];
    const float* g2b2   = (const float*)d_in[22];
    const float* g2w3   = (const float*)d_in[23];
    const float* g2b3   = (const float*)d_in[24];
    const float* bn2g   = (const float*)d_in[25];
    const float* bn2b   = (const float*)d_in[26];
    float* out = (float*)d_out;

    cudaFuncSetAttribute(k_gated2, cudaFuncAttributeMaxDynamicSharedMemorySize, 188416);

    k_zero<<<64, 256>>>();
    k_front<<<(NN + 7)/8, 256>>>(X, rp_w, rp_b, g1w1, g1b1, g1w2, g1b2, g1w3, g1b3);
    k_bnfinal<<<4, 256>>>(0, bn0g, bn0b, 1.f/(float)(NN*TT));
    k_xn<<<(NN*CT + 255)/256, 256>>>();
    k_gemm<<<dim3((NN + 127)/128, HF/128), 256>>>(gatw);
    k_eler<<<NN, 128>>>(attnl, attnr);
    k_count<<<(EE + 255)/256, 256>>>(dst);
    k_scan<<<1, 1024>>>();
    k_fill<<<(EE + 255)/256, 256>>>(src, dst);
    k_agg<<<(NN*32 + 255)/256, 256>>>(gatb);
    k_bn1stats<<<dim3(4, 40), 256>>>();
    k_bnfinal<<<4, 256>>>(1, bn1g, bn1b, 1.f/(float)NN);
    k_gated2<<<(NN + 7)/8, 256, 188416>>>(g2w1, g2b1, g2w2, g2b2, g2w3, g2b3);
    k_bnfinal<<<4, 256>>>(2, bn2g, bn2b, 1.f/(float)(NN*TT));
    k_out<<<(NN*CT + 255)/256, 256>>>(out);
}

// round 2
// speedup vs baseline: 1.1295x; 1.1295x over previous
#include <cuda_runtime.h>
#include <cuda_bf16.h>
#include <math.h>

#define NN 20000
#define CC 32
#define TT 8
#define HH 4
#define FF 256
#define HF 1024
#define EE 320000
#define CT 256
#define BEPS 1e-5f
#define SLOPE 0.2f

#define MPAD 20096          // 157 * 128
#define KP 768              // 3 * 256 packed-K

// ---------------- scratch (static device globals; no runtime alloc) ----------
__device__ float d_res[NN*CT];
__device__ float d_g1[NN*CT];
__device__ float d_xn[NN*CT];
__device__ float d_h[NN*HF];
__device__ float d_rst[NN*HF];
__device__ float d_el[NN*HH];
__device__ float d_er[NN*HH];
__device__ int   d_counts[NN];
__device__ int   d_rowstart[NN+1];
__device__ int   d_wptr[NN];
__device__ int   d_colsrc[EE];
__device__ float d_bn0sum[64];
__device__ float d_bn1sum[2048];
__device__ float d_bn2sum[64];
__device__ float d_scale[HF];
__device__ float d_shift[HF];
__device__ __nv_bfloat16 d_apk[(size_t)MPAD*KP];   // zero-init rows >= NN stay zero
__device__ __nv_bfloat16 d_bpk[(size_t)HF*KP];

// ---------------- utility ----------------------------------------------------
__global__ void k_zero() {
    int stride = gridDim.x * blockDim.x;
    int i0 = blockIdx.x * blockDim.x + threadIdx.x;
    for (int i = i0; i < NN; i += stride) d_counts[i] = 0;
    for (int i = i0; i < 2048; i += stride) d_bn1sum[i] = 0.f;
    for (int i = i0; i < 64; i += stride) { d_bn0sum[i] = 0.f; d_bn2sum[i] = 0.f; }
}

__global__ void k_bnfinal(int stage, const float* __restrict__ gamma,
                          const float* __restrict__ beta, float invM) {
    float* sums = (stage == 0) ? d_bn0sum : (stage == 1 ? d_bn1sum : d_bn2sum);
    int nf = (stage == 1) ? 1024 : 32;
    int f = blockIdx.x * blockDim.x + threadIdx.x;
    if (f < nf) {
        float mean = sums[f] * invM;
        float var  = sums[nf + f] * invM - mean * mean;
        float a = gamma[f] * rsqrtf(var + BEPS);
        d_scale[f] = a;
        d_shift[f] = beta[f] - mean * a;
    }
}

// ---------------- front: residual proj + gated_conv1 + bn0 stats -------------
__global__ __launch_bounds__(256) void k_front(
    const float* __restrict__ X,
    const float* __restrict__ rp_w, const float* __restrict__ rp_b,
    const float* __restrict__ w1, const float* __restrict__ b1,
    const float* __restrict__ w2, const float* __restrict__ b2,
    const float* __restrict__ w3, const float* __restrict__ b3)
{
    __shared__ float s_rp[CC*CC];
    __shared__ float s_w1[CC*CC*3];
    __shared__ float s_w2[CC*CC*3];
    __shared__ float s_w3[CC*CC*3];
    __shared__ float s_x[8][CC][TT];

    int tid = threadIdx.x;
    for (int i = tid; i < CC*CC; i += 256) s_rp[i] = rp_w[i];
    for (int i = tid; i < CC*CC*3; i += 256) {
        s_w1[i] = w1[i]; s_w2[i] = w2[i]; s_w3[i] = w3[i];
    }
    int node0 = blockIdx.x * 8;
    for (int i = tid; i < 8*CT; i += 256) {
        int nl = i / CT, r = i % CT;
        int n = node0 + nl;
        s_x[nl][r >> 3][r & 7] = (n < NN) ? X[n*CT + r] : 0.f;
    }
    __syncthreads();

    int c = tid >> 3, t = tid & 7;
    float gv[8];
    float bb1 = b1[c], bb2 = b2[c], bb3 = b3[c], bbr = rp_b[c];
    for (int nl = 0; nl < 8; nl++) {
        int n = node0 + nl;
        float a1 = bb1, a2 = bb2, a3 = bb3, ar = bbr;
        #pragma unroll
        for (int ci = 0; ci < CC; ci++) {
            float x0 = s_x[nl][ci][t];
            float xm = (t > 0) ? s_x[nl][ci][t-1] : 0.f;
            float xp = (t < 7) ? s_x[nl][ci][t+1] : 0.f;
            ar += s_rp[c*CC + ci] * x0;
            int wb = (c*CC + ci) * 3;
            a1 += s_w1[wb]*xm + s_w1[wb+1]*x0 + s_w1[wb+2]*xp;
            a2 += s_w2[wb]*xm + s_w2[wb+1]*x0 + s_w2[wb+2]*xp;
            a3 += s_w3[wb]*xm + s_w3[wb+1]*x0 + s_w3[wb+2]*xp;
        }
        float sig = 1.f / (1.f + expf(-a2));
        float g = a1 * sig + a3;
        g = g > 0.f ? g : 0.f;
        gv[nl] = g;
        if (n < NN) {
            d_res[n*CT + c*TT + t] = ar;
            d_g1 [n*CT + c*TT + t] = g;
        } else gv[nl] = 0.f;
    }
    __syncthreads();
    float* sred = (float*)s_x;
    if (tid < 64) sred[tid] = 0.f;
    __syncthreads();
    float ls = 0.f, lq = 0.f;
    #pragma unroll
    for (int nl = 0; nl < 8; nl++) { ls += gv[nl]; lq += gv[nl]*gv[nl]; }
    atomicAdd(&sred[c], ls);
    atomicAdd(&sred[32 + c], lq);
    __syncthreads();
    if (tid < 32) {
        atomicAdd(&d_bn0sum[tid],      sred[tid]);
        atomicAdd(&d_bn0sum[32 + tid], sred[32 + tid]);
    }
}

// ---------------- pack A: bn0 apply + bf16 hi/lo split, K-concat ---------------
__global__ void k_packA() {
    int i = blockIdx.x * blockDim.x + threadIdx.x;
    if (i < NN*CT) {
        int n = i >> 8, k = i & 255;
        int c = (k >> 3) & 31;
        float a = d_g1[i] * d_scale[c] + d_shift[c];
        __nv_bfloat16 ah = __float2bfloat16(a);
        float alr = a - __bfloat162float(ah);
        __nv_bfloat16 al = __float2bfloat16(alr);
        size_t base = (size_t)n * KP;
        d_apk[base + k]        = ah;
        d_apk[base + 256 + k]  = al;
        d_apk[base + 512 + k]  = ah;
    }
}

// ---------------- pack B: weights bf16 hi/lo split, K-concat -------------------
__global__ void k_packB(const float* __restrict__ W) {
    int i = blockIdx.x * blockDim.x + threadIdx.x;
    if (i < HF*256) {
        int o = i >> 8, k = i & 255;
        float b = W[i];
        __nv_bfloat16 bh = __float2bfloat16(b);
        float blr = b - __bfloat162float(bh);
        __nv_bfloat16 bl = __float2bfloat16(blr);
        size_t base = (size_t)o * KP;
        d_bpk[base + k]        = bh;
        d_bpk[base + 256 + k]  = bh;
        d_bpk[base + 512 + k]  = bl;
    }
}

// ---------------- tensor-core GEMM: h = A' @ B'^T (bf16x3, fp32 acc) ----------
// M=20096(pad), N=1024, K=768. Block tile 128x128, 8 warps (2x4), warp 64x32.
#define SAPITCH 72   // bf16 elements per smem row (144B, conflict-free frags)

__device__ __forceinline__ void mma16816(float* c, const unsigned* a, const unsigned* b) {
    asm volatile(
        "mma.sync.aligned.m16n8k16.row.col.f32.bf16.bf16.f32 "
        "{%0,%1,%2,%3}, {%4,%5,%6,%7}, {%8,%9}, {%0,%1,%2,%3};\n"
        : "+f"(c[0]), "+f"(c[1]), "+f"(c[2]), "+f"(c[3])
        : "r"(a[0]), "r"(a[1]), "r"(a[2]), "r"(a[3]), "r"(b[0]), "r"(b[1]));
}

__global__ __launch_bounds__(256, 2) void k_gemm_tc() {
    __shared__ __align__(16) __nv_bfloat16 As[128 * SAPITCH];
    __shared__ __align__(16) __nv_bfloat16 Bs[128 * SAPITCH];

    int tid = threadIdx.x;
    int m0 = blockIdx.x * 128, n0 = blockIdx.y * 128;
    int w = tid >> 5, lane = tid & 31;
    int wm = (w >> 2) * 64, wn = (w & 3) * 32;
    int g = lane >> 2, t = lane & 3;

    float acc[4][4][4];
    #pragma unroll
    for (int i = 0; i < 4; i++)
        #pragma unroll
        for (int j = 0; j < 4; j++)
            #pragma unroll
            for (int q = 0; q < 4; q++) acc[i][j][q] = 0.f;

    for (int k0 = 0; k0 < KP; k0 += 64) {
        // load tiles: 128 rows x 64 bf16 = 1024 16B-chunks each; 4 per thread
        #pragma unroll
        for (int r = 0; r < 4; r++) {
            int ch = tid + r * 256;
            int row = ch >> 3, ci = ch & 7;
            uint4 va = *(const uint4*)&d_apk[(size_t)(m0 + row) * KP + k0 + ci * 8];
            *(uint4*)&As[row * SAPITCH + ci * 8] = va;
            uint4 vb = *(const uint4*)&d_bpk[(size_t)(n0 + row) * KP + k0 + ci * 8];
            *(uint4*)&Bs[row * SAPITCH + ci * 8] = vb;
        }
        __syncthreads();

        #pragma unroll
        for (int kk = 0; kk < 4; kk++) {
            int kb = kk * 16;
            unsigned afr[4][4];
            #pragma unroll
            for (int mi = 0; mi < 4; mi++) {
                int r0 = wm + mi * 16 + g;
                afr[mi][0] = *(const unsigned*)&As[r0       * SAPITCH + kb + 2*t];
                afr[mi][1] = *(const unsigned*)&As[(r0 + 8) * SAPITCH + kb + 2*t];
                afr[mi][2] = *(const unsigned*)&As[r0       * SAPITCH + kb + 2*t + 8];
                afr[mi][3] = *(const unsigned*)&As[(r0 + 8) * SAPITCH + kb + 2*t + 8];
            }
            unsigned bfr[4][2];
            #pragma unroll
            for (int nj = 0; nj < 4; nj++) {
                int br = wn + nj * 8 + g;
                bfr[nj][0] = *(const unsigned*)&Bs[br * SAPITCH + kb + 2*t];
                bfr[nj][1] = *(const unsigned*)&Bs[br * SAPITCH + kb + 2*t + 8];
            }
            #pragma unroll
            for (int mi = 0; mi < 4; mi++)
                #pragma unroll
                for (int nj = 0; nj < 4; nj++)
                    mma16816(acc[mi][nj], afr[mi], bfr[nj]);
        }
        __syncthreads();
    }

    // epilogue
    #pragma unroll
    for (int mi = 0; mi < 4; mi++) {
        int r0 = m0 + wm + mi * 16 + g;
        #pragma unroll
        for (int nj = 0; nj < 4; nj++) {
            int col = n0 + wn + nj * 8 + 2 * t;
            if (r0 < NN) {
                d_h[(size_t)r0 * HF + col]     = acc[mi][nj][0];
                d_h[(size_t)r0 * HF + col + 1] = acc[mi][nj][1];
            }
            if (r0 + 8 < NN) {
                d_h[(size_t)(r0 + 8) * HF + col]     = acc[mi][nj][2];
                d_h[(size_t)(r0 + 8) * HF + col + 1] = acc[mi][nj][3];
            }
        }
    }
}

// ---------------- el / er -----------------------------------------------------
__global__ __launch_bounds__(128) void k_eler(const float* __restrict__ attn_l,
                                              const float* __restrict__ attn_r) {
    int n = blockIdx.x;
    int w = threadIdx.x >> 5, lane = threadIdx.x & 31;
    const float* hp = &d_h[n*HF + w*FF];
    float sl = 0.f, sr = 0.f;
    #pragma unroll
    for (int f = lane; f < FF; f += 32) {
        float hv = hp[f];
        sl += hv * __ldg(&attn_l[w*FF + f]);
        sr += hv * __ldg(&attn_r[w*FF + f]);
    }
    #pragma unroll
    for (int off = 16; off; off >>= 1) {
        sl += __shfl_down_sync(0xffffffffu, sl, off);
        sr += __shfl_down_sync(0xffffffffu, sr, off);
    }
    if (lane == 0) { d_el[n*HH + w] = sl; d_er[n*HH + w] = sr; }
}

// ---------------- CSR build ---------------------------------------------------
__global__ void k_count(const int* __restrict__ dst) {
    int e = blockIdx.x * blockDim.x + threadIdx.x;
    if (e < EE) atomicAdd(&d_counts[dst[e]], 1);
}

__global__ __launch_bounds__(1024) void k_scan() {
    __shared__ int part[1024];
    int tid = threadIdx.x;
    int beg = tid * 20, end = min(beg + 20, NN);
    int s = 0;
    for (int i = beg; i < end; i++) s += d_counts[i];
    part[tid] = s;
    __syncthreads();
    for (int off = 1; off < 1024; off <<= 1) {
        int v = 0;
        if (tid >= off) v = part[tid - off];
        __syncthreads();
        if (tid >= off) part[tid] += v;
        __syncthreads();
    }
    int run = (tid == 0) ? 0 : part[tid - 1];
    for (int i = beg; i < end; i++) {
        d_rowstart[i] = run; d_wptr[i] = run;
        run += d_counts[i];
    }
    if (tid == 1023) d_rowstart[NN] = run;
}

__global__ void k_fill(const int* __restrict__ src, const int* __restrict__ dst) {
    int e = blockIdx.x * blockDim.x + threadIdx.x;
    if (e < EE) {
        int p = atomicAdd(&d_wptr[dst[e]], 1);
        d_colsrc[p] = src[e];
    }
}

// ---------------- GAT aggregation: warp per dst node --------------------------
__device__ __forceinline__ float lrelu(float x) { return x > 0.f ? x : SLOPE * x; }

__global__ __launch_bounds__(256) void k_agg(const float* __restrict__ bias) {
    int n = (blockIdx.x * blockDim.x + threadIdx.x) >> 5;
    int lane = threadIdx.x & 31;
    if (n >= NN) return;
    int beg = d_rowstart[n], end = d_rowstart[n+1];
    float er0 = d_er[n*4+0], er1 = d_er[n*4+1], er2 = d_er[n*4+2], er3 = d_er[n*4+3];

    float m0 = -1e30f, m1 = -1e30f, m2 = -1e30f, m3 = -1e30f;
    for (int j = beg + lane; j < end; j += 32) {
        int s = d_colsrc[j];
        m0 = fmaxf(m0, lrelu(d_el[s*4+0] + er0));
        m1 = fmaxf(m1, lrelu(d_el[s*4+1] + er1));
        m2 = fmaxf(m2, lrelu(d_el[s*4+2] + er2));
        m3 = fmaxf(m3, lrelu(d_el[s*4+3] + er3));
    }
    #pragma unroll
    for (int off = 16; off; off >>= 1) {
        m0 = fmaxf(m0, __shfl_xor_sync(0xffffffffu, m0, off));
        m1 = fmaxf(m1, __shfl_xor_sync(0xffffffffu, m1, off));
        m2 = fmaxf(m2, __shfl_xor_sync(0xffffffffu, m2, off));
        m3 = fmaxf(m3, __shfl_xor_sync(0xffffffffu, m3, off));
    }
    float s0 = 0.f, s1 = 0.f, s2 = 0.f, s3 = 0.f;
    for (int j = beg + lane; j < end; j += 32) {
        int s = d_colsrc[j];
        s0 += expf(lrelu(d_el[s*4+0] + er0) - m0);
        s1 += expf(lrelu(d_el[s*4+1] + er1) - m1);
        s2 += expf(lrelu(d_el[s*4+2] + er2) - m2);
        s3 += expf(lrelu(d_el[s*4+3] + er3) - m3);
    }
    #pragma unroll
    for (int off = 16; off; off >>= 1) {
        s0 += __shfl_xor_sync(0xffffffffu, s0, off);
        s1 += __shfl_xor_sync(0xffffffffu, s1, off);
        s2 += __shfl_xor_sync(0xffffffffu, s2, off);
        s3 += __shfl_xor_sync(0xffffffffu, s3, off);
    }
    float i0 = s0 > 0.f ? 1.f/s0 : 0.f;
    float i1 = s1 > 0.f ? 1.f/s1 : 0.f;
    float i2 = s2 > 0.f ? 1.f/s2 : 0.f;
    float i3 = s3 > 0.f ? 1.f/s3 : 0.f;

    float acc[32];
    #pragma unroll
    for (int i = 0; i < 32; i++) acc[i] = 0.f;

    for (int j = beg; j < end; j++) {
        int s = d_colsrc[j];
        float w0 = expf(lrelu(d_el[s*4+0] + er0) - m0) * i0;
        float w1 = expf(lrelu(d_el[s*4+1] + er1) - m1) * i1;
        float w2 = expf(lrelu(d_el[s*4+2] + er2) - m2) * i2;
        float w3 = expf(lrelu(d_el[s*4+3] + er3) - m3) * i3;
        const float* hp = &d_h[s*HF + lane];
        #pragma unroll
        for (int i = 0; i < 32; i++) {
            float wv = (i < 8) ? w0 : (i < 16) ? w1 : (i < 24) ? w2 : w3;
            acc[i] += wv * hp[i*32];
        }
    }
    #pragma unroll
    for (int i = 0; i < 32; i++) {
        int f = i*32 + lane;
        float v = acc[i] + __ldg(&bias[f]);
        d_rst[n*HF + f] = v > 0.f ? v : 0.f;
    }
}

// ---------------- bn1 stats (over N, per feature) -----------------------------
__global__ __launch_bounds__(256) void k_bn1stats() {
    int f = blockIdx.x * 256 + threadIdx.x;
    int n0 = blockIdx.y * 500;
    float s = 0.f, q = 0.f;
    for (int n = n0; n < n0 + 500; n++) {
        float v = d_rst[n*HF + f];
        s += v; q += v*v;
    }
    atomicAdd(&d_bn1sum[f], s);
    atomicAdd(&d_bn1sum[1024 + f], q);
}

// ---------------- gated_conv2 (+bn1 apply on input, +bn2 stats) ---------------
__global__ __launch_bounds__(256) void k_gated2(
    const float* __restrict__ w1, const float* __restrict__ b1,
    const float* __restrict__ w2, const float* __restrict__ b2,
    const float* __restrict__ w3, const float* __restrict__ b3)
{
    extern __shared__ float sm[];
    float* sw1 = sm;
    float* sw2 = sm + 12288;
    float* sw3 = sm + 24576;
    float* sy  = sm + 36864;   // [8][128][10], time-padded

    int tid = threadIdx.x;
    for (int i = tid; i < 12288; i += 256) {
        sw1[i] = w1[i]; sw2[i] = w2[i]; sw3[i] = w3[i];
    }
    int node0 = blockIdx.x * 8;
    for (int i = tid; i < 8*1024; i += 256) {
        int nl = i >> 10, f = i & 1023;
        int n = node0 + nl;
        float v = (n < NN) ? d_rst[n*HF + f] * d_scale[f] + d_shift[f] : 0.f;
        int ci = f >> 3, t = f & 7;
        sy[(nl*128 + ci)*10 + t + 1] = v;
    }
    for (int i = tid; i < 8*128; i += 256) { sy[i*10] = 0.f; sy[i*10 + 9] = 0.f; }
    __syncthreads();

    int c = tid >> 3, t = tid & 7;
    float a1[8], a2[8], a3[8];
    float bb1 = b1[c], bb2 = b2[c], bb3 = b3[c];
    #pragma unroll
    for (int nl = 0; nl < 8; nl++) { a1[nl] = bb1; a2[nl] = bb2; a3[nl] = bb3; }

    for (int ci = 0; ci < 128; ci++) {
        int wb = (c*128 + ci)*3;
        float w10 = sw1[wb], w11 = sw1[wb+1], w12 = sw1[wb+2];
        float w20 = sw2[wb], w21 = sw2[wb+1], w22 = sw2[wb+2];
        float w30 = sw3[wb], w31 = sw3[wb+1], w32 = sw3[wb+2];
        #pragma unroll
        for (int nl = 0; nl < 8; nl++) {
            const float* xp = &sy[(nl*128 + ci)*10 + t];
            float x0 = xp[0], x1 = xp[1], x2 = xp[2];
            a1[nl] += w10*x0 + w11*x1 + w12*x2;
            a2[nl] += w20*x0 + w21*x1 + w22*x2;
            a3[nl] += w30*x0 + w31*x1 + w32*x2;
        }
    }
    float gv[8];
    #pragma unroll
    for (int nl = 0; nl < 8; nl++) {
        int n = node0 + nl;
        float sig = 1.f / (1.f + expf(-a2[nl]));
        float g = a1[nl]*sig + a3[nl];
        g = g > 0.f ? g : 0.f;
        gv[nl] = g;
        if (n < NN) d_xn[n*CT + c*TT + t] = g;
        else gv[nl] = 0.f;
    }
    __syncthreads();
    float* sred = sm;
    if (tid < 64) sred[tid] = 0.f;
    __syncthreads();
    float ls = 0.f, lq = 0.f;
    #pragma unroll
    for (int nl = 0; nl < 8; nl++) { ls += gv[nl]; lq += gv[nl]*gv[nl]; }
    atomicAdd(&sred[c], ls);
    atomicAdd(&sred[32 + c], lq);
    __syncthreads();
    if (tid < 32) {
        atomicAdd(&d_bn2sum[tid],      sred[tid]);
        atomicAdd(&d_bn2sum[32 + tid], sred[32 + tid]);
    }
}

// ---------------- final: bn2 apply + residual + relu --------------------------
__global__ void k_out(float* __restrict__ out) {
    int i = blockIdx.x * blockDim.x + threadIdx.x;
    if (i < NN*CT) {
        int c = (i >> 3) & 31;
        float v = d_xn[i] * d_scale[c] + d_shift[c] + d_res[i];
        out[i] = v > 0.f ? v : 0.f;
    }
}

// ---------------- launch ------------------------------------------------------
extern "C" void kernel_launch(void* const* d_in, const int* in_sizes, int n_in,
                              void* d_out, int out_size) {
    const float* X      = (const float*)d_in[0];
    const int*   src    = (const int*)  d_in[1];
    const int*   dst    = (const int*)  d_in[2];
    const float* rp_w   = (const float*)d_in[3];
    const float* rp_b   = (const float*)d_in[4];
    const float* g1w1   = (const float*)d_in[5];
    const float* g1b1   = (const float*)d_in[6];
    const float* g1w2   = (const float*)d_in[7];
    const float* g1b2   = (const float*)d_in[8];
    const float* g1w3   = (const float*)d_in[9];
    const float* g1b3   = (const float*)d_in[10];
    const float* bn0g   = (const float*)d_in[11];
    const float* bn0b   = (const float*)d_in[12];
    const float* gatw   = (const float*)d_in[13];
    const float* attnl  = (const float*)d_in[14];
    const float* attnr  = (const float*)d_in[15];
    const float* gatb   = (const float*)d_in[16];
    const float* bn1g   = (const float*)d_in[17];
    const float* bn1b   = (const float*)d_in[18];
    const float* g2w1   = (const float*)d_in[19];
    const float* g2b1   = (const float*)d_in[20];
    const float* g2w2   = (const float*)d_in[21];
    const float* g2b2   = (const float*)d_in[22];
    const float* g2w3   = (const float*)d_in[23];
    const float* g2b3   = (const float*)d_in[24];
    const float* bn2g   = (const float*)d_in[25];
    const float* bn2b   = (const float*)d_in[26];
    float* out = (float*)d_out;

    cudaFuncSetAttribute(k_gated2, cudaFuncAttributeMaxDynamicSharedMemorySize, 188416);

    k_zero<<<64, 256>>>();
    k_front<<<(NN + 7)/8, 256>>>(X, rp_w, rp_b, g1w1, g1b1, g1w2, g1b2, g1w3, g1b3);
    k_packB<<<(HF*256 + 255)/256, 256>>>(gatw);
    k_bnfinal<<<4, 256>>>(0, bn0g, bn0b, 1.f/(float)(NN*TT));
    k_packA<<<(NN*CT + 255)/256, 256>>>();
    k_gemm_tc<<<dim3(MPAD/128, HF/128), 256>>>();
    k_eler<<<NN, 128>>>(attnl, attnr);
    k_count<<<(EE + 255)/256, 256>>>(dst);
    k_scan<<<1, 1024>>>();
    k_fill<<<(EE + 255)/256, 256>>>(src, dst);
    k_agg<<<(NN*32 + 255)/256, 256>>>(gatb);
    k_bn1stats<<<dim3(4, 40), 256>>>();
    k_bnfinal<<<4, 256>>>(1, bn1g, bn1b, 1.f/(float)NN);
    k_gated2<<<(NN + 7)/8, 256, 188416>>>(g2w1, g2b1, g2w2, g2b2, g2w3, g2b3);
    k_bnfinal<<<4, 256>>>(2, bn2g, bn2b, 1.f/(float)(NN*TT));
    k_out<<<(NN*CT + 255)/256, 256>>>(out);
}

// round 3
// speedup vs baseline: 1.3717x; 1.2144x over previous
#include <cuda_runtime.h>
#include <cuda_bf16.h>
#include <math.h>
#include <stdint.h>

#define NN 20000
#define CC 32
#define TT 8
#define HH 4
#define FF 256
#define HF 1024
#define EE 320000
#define CT 256
#define BEPS 1e-5f
#define SLOPE 0.2f

#define MPAD 20096          // 157 * 128
#define KP 768              // 3 * 256 packed-K
#define SAPITCH 72

typedef unsigned long long ull;

// ---------------- scratch ----------------
__device__ float d_res[NN*CT];
__device__ float d_g1[NN*CT];
__device__ float d_xn[NN*CT];
__device__ float d_h[NN*HF];
__device__ float d_rst[NN*HF];
__device__ float d_el[NN*HH];
__device__ float d_er[NN*HH];
__device__ int   d_counts[NN];
__device__ int   d_rowstart[NN+1];
__device__ int   d_wptr[NN];
__device__ int   d_colsrc[EE];
__device__ float d_bn0sum[64];
__device__ float d_bn1sum[2048];
__device__ float d_bn2sum[64];
__device__ __nv_bfloat16 d_apk[(size_t)MPAD*KP];   // rows >= NN stay zero
__device__ __nv_bfloat16 d_bpk[(size_t)HF*KP];

// ---------------- f32x2 helpers ----------------
__device__ __forceinline__ void ffma2(ull& d, ull a, ull b) {
    asm("fma.rn.f32x2 %0, %1, %2, %0;" : "+l"(d) : "l"(a), "l"(b));
}
__device__ __forceinline__ ull dup2(float v) {
    ull r; asm("mov.b64 %0, {%1, %1};" : "=l"(r) : "f"(v)); return r;
}
__device__ __forceinline__ void unpk2(ull v, float& lo, float& hi) {
    asm("mov.b64 {%0, %1}, %2;" : "=f"(lo), "=f"(hi) : "l"(v));
}
__device__ __forceinline__ void cpasync16(uint32_t saddr, const void* g) {
    asm volatile("cp.async.cg.shared.global [%0], [%1], 16;" :: "r"(saddr), "l"(g));
}

// ---------------- front: residual + gated_conv1 + bn0 stats (f32x2) ----------
__global__ __launch_bounds__(256) void k_front(
    const float* __restrict__ X,
    const float* __restrict__ rp_w, const float* __restrict__ rp_b,
    const float* __restrict__ w1, const float* __restrict__ b1,
    const float* __restrict__ w2, const float* __restrict__ b2,
    const float* __restrict__ w3, const float* __restrict__ b3)
{
    extern __shared__ __align__(16) float fsm[];
    float* s_rp2 = fsm;                  // 2048
    float* s_w12 = fsm + 2048;           // 6144
    float* s_w22 = fsm + 8192;           // 6144
    float* s_w32 = fsm + 14336;          // 6144
    float* s_x2  = fsm + 20480;          // 2048
    // total 22528 floats = 90112 B

    int tid = threadIdx.x;
    for (int i = tid; i < CC*CC; i += 256) { float v = rp_w[i]; s_rp2[2*i] = v; s_rp2[2*i+1] = v; }
    for (int i = tid; i < CC*CC*3; i += 256) {
        float v1 = w1[i]; s_w12[2*i] = v1; s_w12[2*i+1] = v1;
        float v2 = w2[i]; s_w22[2*i] = v2; s_w22[2*i+1] = v2;
        float v3 = w3[i]; s_w32[2*i] = v3; s_w32[2*i+1] = v3;
    }
    int node0 = blockIdx.x * 8;
    for (int i = tid; i < 8*CT; i += 256) {
        int nl = i >> 8, r = i & 255;
        int n = node0 + nl;
        float v = (n < NN) ? X[n*CT + r] : 0.f;
        int c_ = r >> 3, t_ = r & 7, p = nl >> 1, par = nl & 1;
        s_x2[((p*CC + c_)*TT + t_)*2 + par] = v;
    }
    __syncthreads();

    int c = tid >> 3, t = tid & 7;
    ull ar[4], a1[4], a2[4], a3[4];
    {
        ull Br = dup2(rp_b[c]), B1 = dup2(b1[c]), B2 = dup2(b2[c]), B3 = dup2(b3[c]);
        #pragma unroll
        for (int p = 0; p < 4; p++) { ar[p] = Br; a1[p] = B1; a2[p] = B2; a3[p] = B3; }
    }

    #pragma unroll 4
    for (int ci = 0; ci < CC; ci++) {
        ull Wr = *(const ull*)&s_rp2[2*(c*CC + ci)];
        const ull* W1p = (const ull*)&s_w12[2*((c*CC + ci)*3)];
        const ull* W2p = (const ull*)&s_w22[2*((c*CC + ci)*3)];
        const ull* W3p = (const ull*)&s_w32[2*((c*CC + ci)*3)];
        ull W10 = W1p[0], W11 = W1p[1], W12 = W1p[2];
        ull W20 = W2p[0], W21 = W2p[1], W22 = W2p[2];
        ull W30 = W3p[0], W31 = W3p[1], W32 = W3p[2];
        #pragma unroll
        for (int p = 0; p < 4; p++) {
            const ull* xb = (const ull*)&s_x2[((p*CC + ci)*TT)*2];
            ull X0 = xb[t];
            ull Xm = (t > 0) ? xb[t-1] : 0ull;
            ull Xp = (t < 7) ? xb[t+1] : 0ull;
            ffma2(ar[p], Wr, X0);
            ffma2(a1[p], W10, Xm); ffma2(a1[p], W11, X0); ffma2(a1[p], W12, Xp);
            ffma2(a2[p], W20, Xm); ffma2(a2[p], W21, X0); ffma2(a2[p], W22, Xp);
            ffma2(a3[p], W30, Xm); ffma2(a3[p], W31, X0); ffma2(a3[p], W32, Xp);
        }
    }

    float gv[8];
    #pragma unroll
    for (int p = 0; p < 4; p++) {
        float arl, arh, a1l, a1h, a2l, a2h, a3l, a3h;
        unpk2(ar[p], arl, arh); unpk2(a1[p], a1l, a1h);
        unpk2(a2[p], a2l, a2h); unpk2(a3[p], a3l, a3h);
        float av[2] = {arl, arh}, v1[2] = {a1l, a1h}, v2[2] = {a2l, a2h}, v3[2] = {a3l, a3h};
        #pragma unroll
        for (int par = 0; par < 2; par++) {
            int nl = 2*p + par;
            int n = node0 + nl;
            float sig = 1.f / (1.f + expf(-v2[par]));
            float g = v1[par]*sig + v3[par];
            g = g > 0.f ? g : 0.f;
            gv[nl] = g;
            if (n < NN) {
                d_res[n*CT + c*TT + t] = av[par];
                d_g1 [n*CT + c*TT + t] = g;
            } else gv[nl] = 0.f;
        }
    }
    __syncthreads();
    float* sred = fsm;
    if (tid < 64) sred[tid] = 0.f;
    __syncthreads();
    float ls = 0.f, lq = 0.f;
    #pragma unroll
    for (int nl = 0; nl < 8; nl++) { ls += gv[nl]; lq += gv[nl]*gv[nl]; }
    atomicAdd(&sred[c], ls);
    atomicAdd(&sred[32 + c], lq);
    __syncthreads();
    if (tid < 32) {
        atomicAdd(&d_bn0sum[tid],      sred[tid]);
        atomicAdd(&d_bn0sum[32 + tid], sred[32 + tid]);
    }
}

// ---------------- pack A (fused bn0 finalize) ----------------
__global__ __launch_bounds__(256) void k_packA(const float* __restrict__ bn0g,
                                               const float* __restrict__ bn0b) {
    __shared__ float ssc[32], ssh[32];
    int tid = threadIdx.x;
    if (tid < 32) {
        float inv = 1.f/(float)(NN*TT);
        float mean = d_bn0sum[tid]*inv;
        float var  = d_bn0sum[32+tid]*inv - mean*mean;
        float a = bn0g[tid]*rsqrtf(var + BEPS);
        ssc[tid] = a; ssh[tid] = bn0b[tid] - mean*a;
    }
    __syncthreads();
    int base = blockIdx.x * 16384;
    for (int o = tid; o < 16384; o += 256) {
        int i = base + o;
        if (i < NN*CT) {
            int n = i >> 8, k = i & 255;
            int c = (k >> 3) & 31;
            float a = d_g1[i]*ssc[c] + ssh[c];
            __nv_bfloat16 ah = __float2bfloat16(a);
            __nv_bfloat16 al = __float2bfloat16(a - __bfloat162float(ah));
            size_t b2 = (size_t)n * KP;
            d_apk[b2 + k]       = ah;
            d_apk[b2 + 256 + k] = al;
            d_apk[b2 + 512 + k] = ah;
        }
    }
}

// ---------------- pack B ----------------
__global__ void k_packB(const float* __restrict__ W) {
    int i = blockIdx.x * blockDim.x + threadIdx.x;
    if (i < HF*256) {
        int o = i >> 8, k = i & 255;
        float b = W[i];
        __nv_bfloat16 bh = __float2bfloat16(b);
        __nv_bfloat16 bl = __float2bfloat16(b - __bfloat162float(bh));
        size_t base = (size_t)o * KP;
        d_bpk[base + k]       = bh;
        d_bpk[base + 256 + k] = bh;
        d_bpk[base + 512 + k] = bl;
    }
}

// ---------------- GEMM (bf16x3) + fused el/er ----------------
__device__ __forceinline__ void mma16816(float* c, const unsigned* a, const unsigned* b) {
    asm volatile(
        "mma.sync.aligned.m16n8k16.row.col.f32.bf16.bf16.f32 "
        "{%0,%1,%2,%3}, {%4,%5,%6,%7}, {%8,%9}, {%0,%1,%2,%3};\n"
        : "+f"(c[0]), "+f"(c[1]), "+f"(c[2]), "+f"(c[3])
        : "r"(a[0]), "r"(a[1]), "r"(a[2]), "r"(a[3]), "r"(b[0]), "r"(b[1]));
}

__global__ __launch_bounds__(256) void k_gemm_tc(const float* __restrict__ attn_l,
                                                 const float* __restrict__ attn_r) {
    extern __shared__ __align__(16) char gsm[];
    __nv_bfloat16* As = (__nv_bfloat16*)gsm;           // [2][128*72]
    __nv_bfloat16* Bs = As + 2*128*SAPITCH;

    int tid = threadIdx.x;
    int m0 = blockIdx.x * 128, n0 = blockIdx.y * 128;
    int w = tid >> 5, lane = tid & 31;
    int wm = (w >> 2) * 64, wn = (w & 3) * 32;
    int g = lane >> 2, t = lane & 3;

    uint32_t sA = (uint32_t)__cvta_generic_to_shared(As);
    uint32_t sB = (uint32_t)__cvta_generic_to_shared(Bs);

    float acc[4][4][4];
    #pragma unroll
    for (int i = 0; i < 4; i++)
        #pragma unroll
        for (int j = 0; j < 4; j++)
            #pragma unroll
            for (int q = 0; q < 4; q++) acc[i][j][q] = 0.f;

    int row4 = tid >> 3, ci4 = tid & 7;   // for loading

    // prologue: tile 0 -> buf 0
    #pragma unroll
    for (int r = 0; r < 4; r++) {
        int row = row4 + r*32;
        cpasync16(sA + (0*128*SAPITCH + row*SAPITCH + ci4*8)*2,
                  &d_apk[(size_t)(m0 + row)*KP + 0 + ci4*8]);
        cpasync16(sB + (0*128*SAPITCH + row*SAPITCH + ci4*8)*2,
                  &d_bpk[(size_t)(n0 + row)*KP + 0 + ci4*8]);
    }
    asm volatile("cp.async.commit_group;");

    for (int it = 0; it < 12; it++) {
        if (it < 11) {
            int k0 = (it + 1) * 64, buf = (it + 1) & 1;
            #pragma unroll
            for (int r = 0; r < 4; r++) {
                int row = row4 + r*32;
                cpasync16(sA + (buf*128*SAPITCH + row*SAPITCH + ci4*8)*2,
                          &d_apk[(size_t)(m0 + row)*KP + k0 + ci4*8]);
                cpasync16(sB + (buf*128*SAPITCH + row*SAPITCH + ci4*8)*2,
                          &d_bpk[(size_t)(n0 + row)*KP + k0 + ci4*8]);
            }
            asm volatile("cp.async.commit_group;");
            asm volatile("cp.async.wait_group 1;");
        } else {
            asm volatile("cp.async.wait_group 0;");
        }
        __syncthreads();

        const __nv_bfloat16* Ab = As + (it & 1)*128*SAPITCH;
        const __nv_bfloat16* Bb = Bs + (it & 1)*128*SAPITCH;
        #pragma unroll
        for (int kk = 0; kk < 4; kk++) {
            int kb = kk * 16;
            unsigned afr[4][4];
            #pragma unroll
            for (int mi = 0; mi < 4; mi++) {
                int r0 = wm + mi*16 + g;
                afr[mi][0] = *(const unsigned*)&Ab[r0      *SAPITCH + kb + 2*t];
                afr[mi][1] = *(const unsigned*)&Ab[(r0 + 8)*SAPITCH + kb + 2*t];
                afr[mi][2] = *(const unsigned*)&Ab[r0      *SAPITCH + kb + 2*t + 8];
                afr[mi][3] = *(const unsigned*)&Ab[(r0 + 8)*SAPITCH + kb + 2*t + 8];
            }
            unsigned bfr[4][2];
            #pragma unroll
            for (int nj = 0; nj < 4; nj++) {
                int br = wn + nj*8 + g;
                bfr[nj][0] = *(const unsigned*)&Bb[br*SAPITCH + kb + 2*t];
                bfr[nj][1] = *(const unsigned*)&Bb[br*SAPITCH + kb + 2*t + 8];
            }
            #pragma unroll
            for (int mi = 0; mi < 4; mi++)
                #pragma unroll
                for (int nj = 0; nj < 4; nj++)
                    mma16816(acc[mi][nj], afr[mi], bfr[nj]);
        }
        __syncthreads();
    }

    // fused el/er partials
    float pel[4][2], per_[4][2];
    #pragma unroll
    for (int mi = 0; mi < 4; mi++) { pel[mi][0]=pel[mi][1]=per_[mi][0]=per_[mi][1]=0.f; }
    #pragma unroll
    for (int mi = 0; mi < 4; mi++)
        #pragma unroll
        for (int nj = 0; nj < 4; nj++) {
            int col = n0 + wn + nj*8 + 2*t;
            float al0 = __ldg(&attn_l[col]), al1 = __ldg(&attn_l[col+1]);
            float ar0 = __ldg(&attn_r[col]), ar1 = __ldg(&attn_r[col+1]);
            pel[mi][0]  += acc[mi][nj][0]*al0 + acc[mi][nj][1]*al1;
            pel[mi][1]  += acc[mi][nj][2]*al0 + acc[mi][nj][3]*al1;
            per_[mi][0] += acc[mi][nj][0]*ar0 + acc[mi][nj][1]*ar1;
            per_[mi][1] += acc[mi][nj][2]*ar0 + acc[mi][nj][3]*ar1;
        }
    #pragma unroll
    for (int mi = 0; mi < 4; mi++)
        #pragma unroll
        for (int h2 = 0; h2 < 2; h2++) {
            pel[mi][h2]  += __shfl_xor_sync(0xffffffffu, pel[mi][h2], 1);
            pel[mi][h2]  += __shfl_xor_sync(0xffffffffu, pel[mi][h2], 2);
            per_[mi][h2] += __shfl_xor_sync(0xffffffffu, per_[mi][h2], 1);
            per_[mi][h2] += __shfl_xor_sync(0xffffffffu, per_[mi][h2], 2);
        }
    int head = n0 >> 8;
    if (t == 0) {
        #pragma unroll
        for (int mi = 0; mi < 4; mi++) {
            int r0 = m0 + wm + mi*16 + g;
            if (r0 < NN)     { atomicAdd(&d_el[r0*4 + head], pel[mi][0]);
                               atomicAdd(&d_er[r0*4 + head], per_[mi][0]); }
            if (r0 + 8 < NN) { atomicAdd(&d_el[(r0+8)*4 + head], pel[mi][1]);
                               atomicAdd(&d_er[(r0+8)*4 + head], per_[mi][1]); }
        }
    }

    // store h
    #pragma unroll
    for (int mi = 0; mi < 4; mi++) {
        int r0 = m0 + wm + mi*16 + g;
        #pragma unroll
        for (int nj = 0; nj < 4; nj++) {
            int col = n0 + wn + nj*8 + 2*t;
            if (r0 < NN) {
                d_h[(size_t)r0*HF + col]     = acc[mi][nj][0];
                d_h[(size_t)r0*HF + col + 1] = acc[mi][nj][1];
            }
            if (r0 + 8 < NN) {
                d_h[(size_t)(r0+8)*HF + col]     = acc[mi][nj][2];
                d_h[(size_t)(r0+8)*HF + col + 1] = acc[mi][nj][3];
            }
        }
    }
}

// ---------------- CSR build ----------------
__global__ void k_count(const int* __restrict__ dst) {
    int e = blockIdx.x * blockDim.x + threadIdx.x;
    if (e < EE) atomicAdd(&d_counts[dst[e]], 1);
}

__global__ __launch_bounds__(1024) void k_scan() {
    __shared__ int part[1024];
    int tid = threadIdx.x;
    int beg = tid * 20, end = min(beg + 20, NN);
    int s = 0;
    for (int i = beg; i < end; i++) s += d_counts[i];
    part[tid] = s;
    __syncthreads();
    for (int off = 1; off < 1024; off <<= 1) {
        int v = 0;
        if (tid >= off) v = part[tid - off];
        __syncthreads();
        if (tid >= off) part[tid] += v;
        __syncthreads();
    }
    int run = (tid == 0) ? 0 : part[tid - 1];
    for (int i = beg; i < end; i++) {
        d_rowstart[i] = run; d_wptr[i] = run;
        run += d_counts[i];
    }
    if (tid == 1023) d_rowstart[NN] = run;
}

__global__ void k_fill(const int* __restrict__ src, const int* __restrict__ dst) {
    int e = blockIdx.x * blockDim.x + threadIdx.x;
    if (e < EE) {
        int p = atomicAdd(&d_wptr[dst[e]], 1);
        d_colsrc[p] = src[e];
    }
}

// ---------------- GAT aggregation ----------------
__device__ __forceinline__ float lrelu(float x) { return x > 0.f ? x : SLOPE * x; }

__global__ __launch_bounds__(256) void k_agg(const float* __restrict__ bias) {
    int n = (blockIdx.x * blockDim.x + threadIdx.x) >> 5;
    int lane = threadIdx.x & 31;
    if (n >= NN) return;
    int beg = d_rowstart[n], end = d_rowstart[n+1];
    float er0 = d_er[n*4+0], er1 = d_er[n*4+1], er2 = d_er[n*4+2], er3 = d_er[n*4+3];

    float e0[4], e1[4], e2[4], e3[4];
    #pragma unroll
    for (int s = 0; s < 4; s++) {
        int j = beg + s*32 + lane;
        if (j < end) {
            int sc = d_colsrc[j];
            e0[s] = lrelu(d_el[sc*4+0] + er0);
            e1[s] = lrelu(d_el[sc*4+1] + er1);
            e2[s] = lrelu(d_el[sc*4+2] + er2);
            e3[s] = lrelu(d_el[sc*4+3] + er3);
        } else { e0[s] = e1[s] = e2[s] = e3[s] = -1e30f; }
    }
    float m0 = -1e30f, m1 = -1e30f, m2 = -1e30f, m3 = -1e30f;
    #pragma unroll
    for (int s = 0; s < 4; s++) {
        m0 = fmaxf(m0, e0[s]); m1 = fmaxf(m1, e1[s]);
        m2 = fmaxf(m2, e2[s]); m3 = fmaxf(m3, e3[s]);
    }
    #pragma unroll
    for (int off = 16; off; off >>= 1) {
        m0 = fmaxf(m0, __shfl_xor_sync(0xffffffffu, m0, off));
        m1 = fmaxf(m1, __shfl_xor_sync(0xffffffffu, m1, off));
        m2 = fmaxf(m2, __shfl_xor_sync(0xffffffffu, m2, off));
        m3 = fmaxf(m3, __shfl_xor_sync(0xffffffffu, m3, off));
    }
    float s0 = 0.f, s1 = 0.f, s2 = 0.f, s3 = 0.f;
    #pragma unroll
    for (int s = 0; s < 4; s++) {
        e0[s] = expf(e0[s] - m0); s0 += e0[s];
        e1[s] = expf(e1[s] - m1); s1 += e1[s];
        e2[s] = expf(e2[s] - m2); s2 += e2[s];
        e3[s] = expf(e3[s] - m3); s3 += e3[s];
    }
    #pragma unroll
    for (int off = 16; off; off >>= 1) {
        s0 += __shfl_xor_sync(0xffffffffu, s0, off);
        s1 += __shfl_xor_sync(0xffffffffu, s1, off);
        s2 += __shfl_xor_sync(0xffffffffu, s2, off);
        s3 += __shfl_xor_sync(0xffffffffu, s3, off);
    }
    float i0 = s0 > 0.f ? 1.f/s0 : 0.f;
    float i1 = s1 > 0.f ? 1.f/s1 : 0.f;
    float i2 = s2 > 0.f ? 1.f/s2 : 0.f;
    float i3 = s3 > 0.f ? 1.f/s3 : 0.f;
    #pragma unroll
    for (int s = 0; s < 4; s++) { e0[s] *= i0; e1[s] *= i1; e2[s] *= i2; e3[s] *= i3; }

    float acc[32];
    #pragma unroll
    for (int i = 0; i < 32; i++) acc[i] = 0.f;

    #pragma unroll
    for (int s = 0; s < 4; s++) {
        int base = beg + s*32;
        int lim = end - base;
        if (lim <= 0) break;
        if (lim > 32) lim = 32;
        for (int u = 0; u < lim; u++) {
            int sc = d_colsrc[base + u];
            float w0 = __shfl_sync(0xffffffffu, e0[s], u);
            float w1 = __shfl_sync(0xffffffffu, e1[s], u);
            float w2 = __shfl_sync(0xffffffffu, e2[s], u);
            float w3 = __shfl_sync(0xffffffffu, e3[s], u);
            const float* hp = &d_h[(size_t)sc*HF + lane];
            #pragma unroll
            for (int i = 0; i < 32; i++) {
                float wv = (i < 8) ? w0 : (i < 16) ? w1 : (i < 24) ? w2 : w3;
                acc[i] += wv * hp[i*32];
            }
        }
    }
    #pragma unroll
    for (int i = 0; i < 32; i++) {
        int f = i*32 + lane;
        float v = acc[i] + __ldg(&bias[f]);
        d_rst[(size_t)n*HF + f] = v > 0.f ? v : 0.f;
    }
}

// ---------------- bn1 stats ----------------
__global__ __launch_bounds__(256) void k_bn1stats() {
    int f = blockIdx.x * 256 + threadIdx.x;
    int n0 = blockIdx.y * 500;
    float s = 0.f, q = 0.f;
    for (int n = n0; n < n0 + 500; n++) {
        float v = d_rst[(size_t)n*HF + f];
        s += v; q += v*v;
    }
    atomicAdd(&d_bn1sum[f], s);
    atomicAdd(&d_bn1sum[1024 + f], q);
}

// ---------------- gated_conv2 (fused bn1 finalize+apply, bn2 stats; f32x2) ----
__global__ __launch_bounds__(256) void k_gated2(
    const float* __restrict__ w1, const float* __restrict__ b1,
    const float* __restrict__ w2, const float* __restrict__ b2,
    const float* __restrict__ w3, const float* __restrict__ b3,
    const float* __restrict__ bn1g, const float* __restrict__ bn1b)
{
    extern __shared__ __align__(16) float sm[];
    float* sw1 = sm;                 // 12288
    float* sw2 = sm + 12288;
    float* sw3 = sm + 24576;
    float* ssc = sm + 36864;         // 1024
    float* ssh = sm + 37888;         // 1024
    float* sy  = sm + 38912;         // 4*128*10*2 = 10240

    int tid = threadIdx.x;
    for (int i = tid; i < 12288; i += 256) { sw1[i] = w1[i]; sw2[i] = w2[i]; sw3[i] = w3[i]; }
    float invN = 1.f/(float)NN;
    for (int f = tid; f < 1024; f += 256) {
        float mean = d_bn1sum[f]*invN;
        float var  = d_bn1sum[1024+f]*invN - mean*mean;
        float a = bn1g[f]*rsqrtf(var + BEPS);
        ssc[f] = a; ssh[f] = bn1b[f] - mean*a;
    }
    for (int i = tid; i < 4*128; i += 256) {
        sy[(i*10 + 0)*2]     = 0.f; sy[(i*10 + 0)*2 + 1] = 0.f;
        sy[(i*10 + 9)*2]     = 0.f; sy[(i*10 + 9)*2 + 1] = 0.f;
    }
    __syncthreads();
    int node0 = blockIdx.x * 8;
    for (int i = tid; i < 8192; i += 256) {
        int nl = i >> 10, f = i & 1023;
        int n = node0 + nl;
        float v = (n < NN) ? d_rst[(size_t)n*HF + f]*ssc[f] + ssh[f] : 0.f;
        int ci = f >> 3, t = f & 7, p = nl >> 1, par = nl & 1;
        sy[((p*128 + ci)*10 + t + 1)*2 + par] = v;
    }
    __syncthreads();

    int c = tid >> 3, t = tid & 7;
    ull a1[4], a2[4], a3[4];
    {
        ull B1 = dup2(b1[c]), B2 = dup2(b2[c]), B3 = dup2(b3[c]);
        #pragma unroll
        for (int p = 0; p < 4; p++) { a1[p] = B1; a2[p] = B2; a3[p] = B3; }
    }

    for (int ci = 0; ci < 128; ci++) {
        int wb = (c*128 + ci)*3;
        ull W10 = dup2(sw1[wb]), W11 = dup2(sw1[wb+1]), W12 = dup2(sw1[wb+2]);
        ull W20 = dup2(sw2[wb]), W21 = dup2(sw2[wb+1]), W22 = dup2(sw2[wb+2]);
        ull W30 = dup2(sw3[wb]), W31 = dup2(sw3[wb+1]), W32 = dup2(sw3[wb+2]);
        #pragma unroll
        for (int p = 0; p < 4; p++) {
            const ull* xb = (const ull*)&sy[((p*128 + ci)*10 + t)*2];
            ull X0 = xb[0], X1 = xb[1], X2 = xb[2];
            ffma2(a1[p], W10, X0); ffma2(a1[p], W11, X1); ffma2(a1[p], W12, X2);
            ffma2(a2[p], W20, X0); ffma2(a2[p], W21, X1); ffma2(a2[p], W22, X2);
            ffma2(a3[p], W30, X0); ffma2(a3[p], W31, X1); ffma2(a3[p], W32, X2);
        }
    }

    float gv[8];
    #pragma unroll
    for (int p = 0; p < 4; p++) {
        float v1l, v1h, v2l, v2h, v3l, v3h;
        unpk2(a1[p], v1l, v1h); unpk2(a2[p], v2l, v2h); unpk2(a3[p], v3l, v3h);
        float v1[2] = {v1l, v1h}, v2[2] = {v2l, v2h}, v3[2] = {v3l, v3h};
        #pragma unroll
        for (int par = 0; par < 2; par++) {
            int nl = 2*p + par;
            int n = node0 + nl;
            float sig = 1.f / (1.f + expf(-v2[par]));
            float g = v1[par]*sig + v3[par];
            g = g > 0.f ? g : 0.f;
            gv[nl] = g;
            if (n < NN) d_xn[n*CT + c*TT + t] = g;
            else gv[nl] = 0.f;
        }
    }
    __syncthreads();
    float* sred = sm;
    if (tid < 64) sred[tid] = 0.f;
    __syncthreads();
    float ls = 0.f, lq = 0.f;
    #pragma unroll
    for (int nl = 0; nl < 8; nl++) { ls += gv[nl]; lq += gv[nl]*gv[nl]; }
    atomicAdd(&sred[c], ls);
    atomicAdd(&sred[32 + c], lq);
    __syncthreads();
    if (tid < 32) {
        atomicAdd(&d_bn2sum[tid],      sred[tid]);
        atomicAdd(&d_bn2sum[32 + tid], sred[32 + tid]);
    }
}

// ---------------- final: bn2 finalize + apply + residual + relu ---------------
__global__ void k_out(float* __restrict__ out, const float* __restrict__ bn2g,
                      const float* __restrict__ bn2b) {
    __shared__ float ssc[32], ssh[32];
    int tid = threadIdx.x;
    if (tid < 32) {
        float inv = 1.f/(float)(NN*TT);
        float mean = d_bn2sum[tid]*inv;
        float var  = d_bn2sum[32+tid]*inv - mean*mean;
        float a = bn2g[tid]*rsqrtf(var + BEPS);
        ssc[tid] = a; ssh[tid] = bn2b[tid] - mean*a;
    }
    __syncthreads();
    int base = blockIdx.x * 2048;
    for (int o = tid; o < 2048; o += 256) {
        int i = base + o;
        if (i < NN*CT) {
            int c = (i >> 3) & 31;
            float v = d_xn[i]*ssc[c] + ssh[c] + d_res[i];
            out[i] = v > 0.f ? v : 0.f;
        }
    }
}

// ---------------- launch ----------------
extern "C" void kernel_launch(void* const* d_in, const int* in_sizes, int n_in,
                              void* d_out, int out_size) {
    const float* X      = (const float*)d_in[0];
    const int*   src    = (const int*)  d_in[1];
    const int*   dst    = (const int*)  d_in[2];
    const float* rp_w   = (const float*)d_in[3];
    const float* rp_b   = (const float*)d_in[4];
    const float* g1w1   = (const float*)d_in[5];
    const float* g1b1   = (const float*)d_in[6];
    const float* g1w2   = (const float*)d_in[7];
    const float* g1b2   = (const float*)d_in[8];
    const float* g1w3   = (const float*)d_in[9];
    const float* g1b3   = (const float*)d_in[10];
    const float* bn0g   = (const float*)d_in[11];
    const float* bn0b   = (const float*)d_in[12];
    const float* gatw   = (const float*)d_in[13];
    const float* attnl  = (const float*)d_in[14];
    const float* attnr  = (const float*)d_in[15];
    const float* gatb   = (const float*)d_in[16];
    const float* bn1g   = (const float*)d_in[17];
    const float* bn1b   = (const float*)d_in[18];
    const float* g2w1   = (const float*)d_in[19];
    const float* g2b1   = (const float*)d_in[20];
    const float* g2w2   = (const float*)d_in[21];
    const float* g2b2   = (const float*)d_in[22];
    const float* g2w3   = (const float*)d_in[23];
    const float* g2b3   = (const float*)d_in[24];
    const float* bn2g   = (const float*)d_in[25];
    const float* bn2b   = (const float*)d_in[26];
    float* out = (float*)d_out;

    static int inited = 0;
    if (!inited) {
        cudaFuncSetAttribute(k_front,   cudaFuncAttributeMaxDynamicSharedMemorySize, 90112);
        cudaFuncSetAttribute(k_gemm_tc, cudaFuncAttributeMaxDynamicSharedMemorySize, 73728);
        cudaFuncSetAttribute(k_gated2,  cudaFuncAttributeMaxDynamicSharedMemorySize, 196608);
        inited = 1;
    }

    void *p_b0, *p_b1, *p_b2, *p_cnt, *p_el, *p_er;
    cudaGetSymbolAddress(&p_b0, d_bn0sum);
    cudaGetSymbolAddress(&p_b1, d_bn1sum);
    cudaGetSymbolAddress(&p_b2, d_bn2sum);
    cudaGetSymbolAddress(&p_cnt, d_counts);
    cudaGetSymbolAddress(&p_el, d_el);
    cudaGetSymbolAddress(&p_er, d_er);
    cudaMemsetAsync(p_b0, 0, 64*sizeof(float));
    cudaMemsetAsync(p_b1, 0, 2048*sizeof(float));
    cudaMemsetAsync(p_b2, 0, 64*sizeof(float));
    cudaMemsetAsync(p_cnt, 0, NN*sizeof(int));
    cudaMemsetAsync(p_el, 0, NN*HH*sizeof(float));
    cudaMemsetAsync(p_er, 0, NN*HH*sizeof(float));

    k_front<<<(NN + 7)/8, 256, 90112>>>(X, rp_w, rp_b, g1w1, g1b1, g1w2, g1b2, g1w3, g1b3);
    k_packB<<<(HF*256 + 255)/256, 256>>>(gatw);
    k_packA<<<(NN*CT + 16383)/16384, 256>>>(bn0g, bn0b);
    k_gemm_tc<<<dim3(MPAD/128, HF/128), 256, 73728>>>(attnl, attnr);
    k_count<<<(EE + 255)/256, 256>>>(dst);
    k_scan<<<1, 1024>>>();
    k_fill<<<(EE + 255)/256, 256>>>(src, dst);
    k_agg<<<(NN*32 + 255)/256, 256>>>(gatb);
    k_bn1stats<<<dim3(4, 40), 256>>>();
    k_gated2<<<(NN + 7)/8, 256, 196608>>>(g2w1, g2b1, g2w2, g2b2, g2w3, g2b3, bn1g, bn1b);
    k_out<<<(NN*CT + 2047)/2048, 256>>>(out, bn2g, bn2b);
}

// round 4
// speedup vs baseline: 1.3721x; 1.0003x over previous
#include <cuda_runtime.h>
#include <cuda_bf16.h>
#include <math.h>
#include <stdint.h>

#define NN 20000
#define CC 32
#define TT 8
#define HH 4
#define FF 256
#define HF 1024
#define EE 320000
#define CT 256
#define BEPS 1e-5f
#define SLOPE 0.2f

#define MPAD 20096
#define KP 512              // packed-K storage width (hi|lo)
#define SAPITCH 72
#define WP 36               // transposed weight pitch (floats)

typedef unsigned long long ull;

// ---------------- scratch ----------------
__device__ float d_res[NN*CT];
__device__ float d_g1[NN*CT];
__device__ float d_xn[NN*CT];
__device__ float d_h[NN*HF];
__device__ float d_rst[NN*HF];
__device__ float d_el[NN*HH];
__device__ float d_er[NN*HH];
__device__ int   d_counts[NN];
__device__ int   d_rowstart[NN+1];
__device__ int   d_wptr[NN];
__device__ int   d_colsrc[EE];
__device__ float d_bn0sum[64];
__device__ float d_bn1sum[2048];
__device__ float d_bn2sum[64];
__device__ __nv_bfloat16 d_apk[(size_t)MPAD*KP];   // rows >= NN stay zero
__device__ __nv_bfloat16 d_bpk[(size_t)HF*KP];

// ---------------- f32x2 helpers ----------------
__device__ __forceinline__ void ffma2(ull& d, ull a, ull b) {
    asm("fma.rn.f32x2 %0, %1, %2, %0;" : "+l"(d) : "l"(a), "l"(b));
}
__device__ __forceinline__ ull dup2(float v) {
    ull r; asm("mov.b64 %0, {%1, %1};" : "=l"(r) : "f"(v)); return r;
}
__device__ __forceinline__ ull pack2(float a, float b) {
    ull r; asm("mov.b64 %0, {%1, %2};" : "=l"(r) : "f"(a), "f"(b)); return r;
}
__device__ __forceinline__ void unpk2(ull v, float& lo, float& hi) {
    asm("mov.b64 {%0, %1}, %2;" : "=f"(lo), "=f"(hi) : "l"(v));
}
__device__ __forceinline__ void f4u2(float4 v, ull& a, ull& b) {
    asm("mov.b64 %0, {%2, %3};\n\tmov.b64 %1, {%4, %5};"
        : "=l"(a), "=l"(b) : "f"(v.x), "f"(v.y), "f"(v.z), "f"(v.w));
}
__device__ __forceinline__ void cpasync16(uint32_t saddr, const void* g) {
    asm volatile("cp.async.cg.shared.global [%0], [%1], 16;" :: "r"(saddr), "l"(g));
}

// ---------------- front: residual + gated_conv1 + bn0 stats -------------------
// warp <-> co quad; lane = nl*4 + t2 (handles t2, t2+4); f32x2 = co pair.
__global__ __launch_bounds__(256) void k_front(
    const float* __restrict__ X,
    const float* __restrict__ rp_w, const float* __restrict__ rp_b,
    const float* __restrict__ w1, const float* __restrict__ b1,
    const float* __restrict__ w2, const float* __restrict__ b2,
    const float* __restrict__ w3, const float* __restrict__ b3)
{
    extern __shared__ __align__(16) float fsm[];
    float* swc = fsm;                    // 288*36 = 10368
    float* srp = fsm + 10368;            // 32*36 = 1152
    float* sx  = fsm + 11520;            // 8*324 = 2592
    // total 14112 floats = 56448 B

    int tid = threadIdx.x;
    for (int i = tid; i < 3072; i += 256) {
        int co = i / 96, r = i % 96, ci = r / 3, k = r % 3;
        swc[(ci*9 + 0 + k)*WP + co] = w1[i];
        swc[(ci*9 + 3 + k)*WP + co] = w2[i];
        swc[(ci*9 + 6 + k)*WP + co] = w3[i];
    }
    for (int i = tid; i < 1024; i += 256) {
        int co = i >> 5, ci = i & 31;
        srp[ci*WP + co] = rp_w[i];
    }
    int node0 = blockIdx.x * 8;
    for (int i = tid; i < 2048; i += 256) {
        int nl = i >> 8, r = i & 255;
        float v = X[(node0 + nl)*256 + r];
        int ci = r >> 3, t = r & 7;
        sx[nl*324 + ci*10 + t + 1] = v;
    }
    {
        int nl = tid >> 5, ci = tid & 31;
        sx[nl*324 + ci*10 + 0] = 0.f;
        sx[nl*324 + ci*10 + 9] = 0.f;
    }
    __syncthreads();

    int w = tid >> 5, lane = tid & 31;
    int coq = w * 4;
    int nl = lane >> 2, t2 = lane & 3;
    const float* xb = &sx[nl*324 + t2];

    ull acc[2][4][2];
    #pragma unroll
    for (int s = 0; s < 2; s++)
        #pragma unroll
        for (int pr = 0; pr < 2; pr++) {
            int c0 = coq + 2*pr;
            acc[s][0][pr] = pack2(b1[c0], b1[c0+1]);
            acc[s][1][pr] = pack2(b2[c0], b2[c0+1]);
            acc[s][2][pr] = pack2(b3[c0], b3[c0+1]);
            acc[s][3][pr] = pack2(rp_b[c0], rp_b[c0+1]);
        }

    #pragma unroll 4
    for (int ci = 0; ci < 32; ci++) {
        ull Xv[2][3];
        #pragma unroll
        for (int k = 0; k < 3; k++) {
            Xv[0][k] = dup2(xb[ci*10 + k]);
            Xv[1][k] = dup2(xb[ci*10 + 4 + k]);
        }
        {
            float4 R = *(const float4*)&srp[ci*WP + coq];
            ull r0, r1; f4u2(R, r0, r1);
            ffma2(acc[0][3][0], r0, Xv[0][1]); ffma2(acc[0][3][1], r1, Xv[0][1]);
            ffma2(acc[1][3][0], r0, Xv[1][1]); ffma2(acc[1][3][1], r1, Xv[1][1]);
        }
        #pragma unroll
        for (int j = 0; j < 3; j++)
            #pragma unroll
            for (int k = 0; k < 3; k++) {
                float4 W = *(const float4*)&swc[(ci*9 + j*3 + k)*WP + coq];
                ull w0, w1v; f4u2(W, w0, w1v);
                ffma2(acc[0][j][0], w0,  Xv[0][k]);
                ffma2(acc[0][j][1], w1v, Xv[0][k]);
                ffma2(acc[1][j][0], w0,  Xv[1][k]);
                ffma2(acc[1][j][1], w1v, Xv[1][k]);
            }
    }

    int n = node0 + nl;
    float gsum[4] = {0.f,0.f,0.f,0.f}, gsq[4] = {0.f,0.f,0.f,0.f};
    #pragma unroll
    for (int s = 0; s < 2; s++) {
        int t = t2 + 4*s;
        #pragma unroll
        for (int pr = 0; pr < 2; pr++) {
            float r0, r1, a10, a11, a20, a21, a30, a31;
            unpk2(acc[s][3][pr], r0, r1);
            unpk2(acc[s][0][pr], a10, a11);
            unpk2(acc[s][1][pr], a20, a21);
            unpk2(acc[s][2][pr], a30, a31);
            int c0 = coq + 2*pr;
            float g0 = a10 * (1.f/(1.f + expf(-a20))) + a30; g0 = g0 > 0.f ? g0 : 0.f;
            float g1 = a11 * (1.f/(1.f + expf(-a21))) + a31; g1 = g1 > 0.f ? g1 : 0.f;
            d_res[n*256 + c0*8 + t]     = r0;
            d_res[n*256 + (c0+1)*8 + t] = r1;
            d_g1 [n*256 + c0*8 + t]     = g0;
            d_g1 [n*256 + (c0+1)*8 + t] = g1;
            gsum[2*pr] += g0;   gsq[2*pr] += g0*g0;
            gsum[2*pr+1] += g1; gsq[2*pr+1] += g1*g1;
        }
    }
    __syncthreads();
    float* sred = fsm;
    if (tid < 64) sred[tid] = 0.f;
    __syncthreads();
    #pragma unroll
    for (int q = 0; q < 4; q++) {
        atomicAdd(&sred[coq + q], gsum[q]);
        atomicAdd(&sred[32 + coq + q], gsq[q]);
    }
    __syncthreads();
    if (tid < 32) {
        atomicAdd(&d_bn0sum[tid],      sred[tid]);
        atomicAdd(&d_bn0sum[32 + tid], sred[32 + tid]);
    }
}

// ---------------- pack A (fused bn0 finalize) ----------------
__global__ __launch_bounds__(256) void k_packA(const float* __restrict__ bn0g,
                                               const float* __restrict__ bn0b) {
    __shared__ float ssc[32], ssh[32];
    int tid = threadIdx.x;
    if (tid < 32) {
        float inv = 1.f/(float)(NN*TT);
        float mean = d_bn0sum[tid]*inv;
        float var  = d_bn0sum[32+tid]*inv - mean*mean;
        float a = bn0g[tid]*rsqrtf(var + BEPS);
        ssc[tid] = a; ssh[tid] = bn0b[tid] - mean*a;
    }
    __syncthreads();
    int base = blockIdx.x * 16384;
    for (int o = tid; o < 16384; o += 256) {
        int i = base + o;
        if (i < NN*CT) {
            int n = i >> 8, k = i & 255;
            int c = (k >> 3) & 31;
            float a = d_g1[i]*ssc[c] + ssh[c];
            __nv_bfloat16 ah = __float2bfloat16(a);
            __nv_bfloat16 al = __float2bfloat16(a - __bfloat162float(ah));
            size_t b2 = (size_t)n * KP;
            d_apk[b2 + k]       = ah;
            d_apk[b2 + 256 + k] = al;
        }
    }
}

// ---------------- pack B ----------------
__global__ void k_packB(const float* __restrict__ W) {
    int i = blockIdx.x * blockDim.x + threadIdx.x;
    if (i < HF*256) {
        int o = i >> 8, k = i & 255;
        float b = W[i];
        __nv_bfloat16 bh = __float2bfloat16(b);
        __nv_bfloat16 bl = __float2bfloat16(b - __bfloat162float(bh));
        size_t base = (size_t)o * KP;
        d_bpk[base + k]       = bh;
        d_bpk[base + 256 + k] = bl;
    }
}

// ---------------- GEMM (bf16x3 via k-remap) + fused el/er ----------------
__device__ __forceinline__ void mma16816(float* c, const unsigned* a, const unsigned* b) {
    asm volatile(
        "mma.sync.aligned.m16n8k16.row.col.f32.bf16.bf16.f32 "
        "{%0,%1,%2,%3}, {%4,%5,%6,%7}, {%8,%9}, {%0,%1,%2,%3};\n"
        : "+f"(c[0]), "+f"(c[1]), "+f"(c[2]), "+f"(c[3])
        : "r"(a[0]), "r"(a[1]), "r"(a[2]), "r"(a[3]), "r"(b[0]), "r"(b[1]));
}

__global__ __launch_bounds__(256) void k_gemm_tc(const float* __restrict__ attn_l,
                                                 const float* __restrict__ attn_r) {
    extern __shared__ __align__(16) char gsm[];
    __nv_bfloat16* As = (__nv_bfloat16*)gsm;           // [2][128*72]
    __nv_bfloat16* Bs = As + 2*128*SAPITCH;

    int tid = threadIdx.x;
    int m0 = blockIdx.x * 128, n0 = blockIdx.y * 128;
    int w = tid >> 5, lane = tid & 31;
    int wm = (w >> 2) * 64, wn = (w & 3) * 32;
    int g = lane >> 2, t = lane & 3;

    uint32_t sA = (uint32_t)__cvta_generic_to_shared(As);
    uint32_t sB = (uint32_t)__cvta_generic_to_shared(Bs);

    float acc[4][4][4];
    #pragma unroll
    for (int i = 0; i < 4; i++)
        #pragma unroll
        for (int j = 0; j < 4; j++)
            #pragma unroll
            for (int q = 0; q < 4; q++) acc[i][j][q] = 0.f;

    int row4 = tid >> 3, ci4 = tid & 7;

    // prologue
    #pragma unroll
    for (int r = 0; r < 4; r++) {
        int row = row4 + r*32;
        cpasync16(sA + (row*SAPITCH + ci4*8)*2,
                  &d_apk[(size_t)(m0 + row)*KP + ci4*8]);
        cpasync16(sB + (row*SAPITCH + ci4*8)*2,
                  &d_bpk[(size_t)(n0 + row)*KP + ci4*8]);
    }
    asm volatile("cp.async.commit_group;");

    for (int it = 0; it < 12; it++) {
        if (it < 11) {
            int k0 = (it + 1) * 64;
            int ka = (k0 < 512) ? k0 : k0 - 512;
            int kb = (k0 < 256) ? k0 : k0 - 256;
            int buf = (it + 1) & 1;
            #pragma unroll
            for (int r = 0; r < 4; r++) {
                int row = row4 + r*32;
                cpasync16(sA + (buf*128*SAPITCH + row*SAPITCH + ci4*8)*2,
                          &d_apk[(size_t)(m0 + row)*KP + ka + ci4*8]);
                cpasync16(sB + (buf*128*SAPITCH + row*SAPITCH + ci4*8)*2,
                          &d_bpk[(size_t)(n0 + row)*KP + kb + ci4*8]);
            }
            asm volatile("cp.async.commit_group;");
            asm volatile("cp.async.wait_group 1;");
        } else {
            asm volatile("cp.async.wait_group 0;");
        }
        __syncthreads();

        const __nv_bfloat16* Ab = As + (it & 1)*128*SAPITCH;
        const __nv_bfloat16* Bb = Bs + (it & 1)*128*SAPITCH;
        #pragma unroll
        for (int kk = 0; kk < 4; kk++) {
            int kbx = kk * 16;
            unsigned afr[4][4];
            #pragma unroll
            for (int mi = 0; mi < 4; mi++) {
                int r0 = wm + mi*16 + g;
                afr[mi][0] = *(const unsigned*)&Ab[r0      *SAPITCH + kbx + 2*t];
                afr[mi][1] = *(const unsigned*)&Ab[(r0 + 8)*SAPITCH + kbx + 2*t];
                afr[mi][2] = *(const unsigned*)&Ab[r0      *SAPITCH + kbx + 2*t + 8];
                afr[mi][3] = *(const unsigned*)&Ab[(r0 + 8)*SAPITCH + kbx + 2*t + 8];
            }
            unsigned bfr[4][2];
            #pragma unroll
            for (int nj = 0; nj < 4; nj++) {
                int br = wn + nj*8 + g;
                bfr[nj][0] = *(const unsigned*)&Bb[br*SAPITCH + kbx + 2*t];
                bfr[nj][1] = *(const unsigned*)&Bb[br*SAPITCH + kbx + 2*t + 8];
            }
            #pragma unroll
            for (int mi = 0; mi < 4; mi++)
                #pragma unroll
                for (int nj = 0; nj < 4; nj++)
                    mma16816(acc[mi][nj], afr[mi], bfr[nj]);
        }
        __syncthreads();
    }

    // fused el/er partials
    float pel[4][2], per_[4][2];
    #pragma unroll
    for (int mi = 0; mi < 4; mi++) { pel[mi][0]=pel[mi][1]=per_[mi][0]=per_[mi][1]=0.f; }
    #pragma unroll
    for (int mi = 0; mi < 4; mi++)
        #pragma unroll
        for (int nj = 0; nj < 4; nj++) {
            int col = n0 + wn + nj*8 + 2*t;
            float al0 = __ldg(&attn_l[col]), al1 = __ldg(&attn_l[col+1]);
            float ar0 = __ldg(&attn_r[col]), ar1 = __ldg(&attn_r[col+1]);
            pel[mi][0]  += acc[mi][nj][0]*al0 + acc[mi][nj][1]*al1;
            pel[mi][1]  += acc[mi][nj][2]*al0 + acc[mi][nj][3]*al1;
            per_[mi][0] += acc[mi][nj][0]*ar0 + acc[mi][nj][1]*ar1;
            per_[mi][1] += acc[mi][nj][2]*ar0 + acc[mi][nj][3]*ar1;
        }
    #pragma unroll
    for (int mi = 0; mi < 4; mi++)
        #pragma unroll
        for (int h2 = 0; h2 < 2; h2++) {
            pel[mi][h2]  += __shfl_xor_sync(0xffffffffu, pel[mi][h2], 1);
            pel[mi][h2]  += __shfl_xor_sync(0xffffffffu, pel[mi][h2], 2);
            per_[mi][h2] += __shfl_xor_sync(0xffffffffu, per_[mi][h2], 1);
            per_[mi][h2] += __shfl_xor_sync(0xffffffffu, per_[mi][h2], 2);
        }
    int head = n0 >> 8;
    if (t == 0) {
        #pragma unroll
        for (int mi = 0; mi < 4; mi++) {
            int r0 = m0 + wm + mi*16 + g;
            if (r0 < NN)     { atomicAdd(&d_el[r0*4 + head], pel[mi][0]);
                               atomicAdd(&d_er[r0*4 + head], per_[mi][0]); }
            if (r0 + 8 < NN) { atomicAdd(&d_el[(r0+8)*4 + head], pel[mi][1]);
                               atomicAdd(&d_er[(r0+8)*4 + head], per_[mi][1]); }
        }
    }

    #pragma unroll
    for (int mi = 0; mi < 4; mi++) {
        int r0 = m0 + wm + mi*16 + g;
        #pragma unroll
        for (int nj = 0; nj < 4; nj++) {
            int col = n0 + wn + nj*8 + 2*t;
            if (r0 < NN) {
                d_h[(size_t)r0*HF + col]     = acc[mi][nj][0];
                d_h[(size_t)r0*HF + col + 1] = acc[mi][nj][1];
            }
            if (r0 + 8 < NN) {
                d_h[(size_t)(r0+8)*HF + col]     = acc[mi][nj][2];
                d_h[(size_t)(r0+8)*HF + col + 1] = acc[mi][nj][3];
            }
        }
    }
}

// ---------------- CSR build ----------------
__global__ void k_count(const int* __restrict__ dst) {
    int e = blockIdx.x * blockDim.x + threadIdx.x;
    if (e < EE) atomicAdd(&d_counts[dst[e]], 1);
}

__global__ __launch_bounds__(1024) void k_scan() {
    __shared__ int part[1024];
    int tid = threadIdx.x;
    int beg = tid * 20, end = min(beg + 20, NN);
    int s = 0;
    for (int i = beg; i < end; i++) s += d_counts[i];
    part[tid] = s;
    __syncthreads();
    for (int off = 1; off < 1024; off <<= 1) {
        int v = 0;
        if (tid >= off) v = part[tid - off];
        __syncthreads();
        if (tid >= off) part[tid] += v;
        __syncthreads();
    }
    int run = (tid == 0) ? 0 : part[tid - 1];
    for (int i = beg; i < end; i++) {
        d_rowstart[i] = run; d_wptr[i] = run;
        run += d_counts[i];
    }
    if (tid == 1023) d_rowstart[NN] = run;
}

__global__ void k_fill(const int* __restrict__ src, const int* __restrict__ dst) {
    int e = blockIdx.x * blockDim.x + threadIdx.x;
    if (e < EE) {
        int p = atomicAdd(&d_wptr[dst[e]], 1);
        d_colsrc[p] = src[e];
    }
}

// ---------------- GAT aggregation ----------------
__device__ __forceinline__ float lrelu(float x) { return x > 0.f ? x : SLOPE * x; }

__global__ __launch_bounds__(256) void k_agg(const float* __restrict__ bias) {
    int n = (blockIdx.x * blockDim.x + threadIdx.x) >> 5;
    int lane = threadIdx.x & 31;
    if (n >= NN) return;
    int beg = d_rowstart[n], end = d_rowstart[n+1];
    float er0 = d_er[n*4+0], er1 = d_er[n*4+1], er2 = d_er[n*4+2], er3 = d_er[n*4+3];

    float e0[4], e1[4], e2[4], e3[4];
    #pragma unroll
    for (int s = 0; s < 4; s++) {
        int j = beg + s*32 + lane;
        if (j < end) {
            int sc = d_colsrc[j];
            e0[s] = lrelu(d_el[sc*4+0] + er0);
            e1[s] = lrelu(d_el[sc*4+1] + er1);
            e2[s] = lrelu(d_el[sc*4+2] + er2);
            e3[s] = lrelu(d_el[sc*4+3] + er3);
        } else { e0[s] = e1[s] = e2[s] = e3[s] = -1e30f; }
    }
    float m0 = -1e30f, m1 = -1e30f, m2 = -1e30f, m3 = -1e30f;
    #pragma unroll
    for (int s = 0; s < 4; s++) {
        m0 = fmaxf(m0, e0[s]); m1 = fmaxf(m1, e1[s]);
        m2 = fmaxf(m2, e2[s]); m3 = fmaxf(m3, e3[s]);
    }
    #pragma unroll
    for (int off = 16; off; off >>= 1) {
        m0 = fmaxf(m0, __shfl_xor_sync(0xffffffffu, m0, off));
        m1 = fmaxf(m1, __shfl_xor_sync(0xffffffffu, m1, off));
        m2 = fmaxf(m2, __shfl_xor_sync(0xffffffffu, m2, off));
        m3 = fmaxf(m3, __shfl_xor_sync(0xffffffffu, m3, off));
    }
    float s0 = 0.f, s1 = 0.f, s2 = 0.f, s3 = 0.f;
    #pragma unroll
    for (int s = 0; s < 4; s++) {
        e0[s] = expf(e0[s] - m0); s0 += e0[s];
        e1[s] = expf(e1[s] - m1); s1 += e1[s];
        e2[s] = expf(e2[s] - m2); s2 += e2[s];
        e3[s] = expf(e3[s] - m3); s3 += e3[s];
    }
    #pragma unroll
    for (int off = 16; off; off >>= 1) {
        s0 += __shfl_xor_sync(0xffffffffu, s0, off);
        s1 += __shfl_xor_sync(0xffffffffu, s1, off);
        s2 += __shfl_xor_sync(0xffffffffu, s2, off);
        s3 += __shfl_xor_sync(0xffffffffu, s3, off);
    }
    float i0 = s0 > 0.f ? 1.f/s0 : 0.f;
    float i1 = s1 > 0.f ? 1.f/s1 : 0.f;
    float i2 = s2 > 0.f ? 1.f/s2 : 0.f;
    float i3 = s3 > 0.f ? 1.f/s3 : 0.f;
    #pragma unroll
    for (int s = 0; s < 4; s++) { e0[s] *= i0; e1[s] *= i1; e2[s] *= i2; e3[s] *= i3; }

    float acc[32];
    #pragma unroll
    for (int i = 0; i < 32; i++) acc[i] = 0.f;

    #pragma unroll
    for (int s = 0; s < 4; s++) {
        int base = beg + s*32;
        int lim = end - base;
        if (lim <= 0) break;
        if (lim > 32) lim = 32;
        for (int u = 0; u < lim; u++) {
            int sc = d_colsrc[base + u];
            float w0 = __shfl_sync(0xffffffffu, e0[s], u);
            float w1 = __shfl_sync(0xffffffffu, e1[s], u);
            float w2 = __shfl_sync(0xffffffffu, e2[s], u);
            float w3 = __shfl_sync(0xffffffffu, e3[s], u);
            const float* hp = &d_h[(size_t)sc*HF + lane];
            #pragma unroll
            for (int i = 0; i < 32; i++) {
                float wv = (i < 8) ? w0 : (i < 16) ? w1 : (i < 24) ? w2 : w3;
                acc[i] += wv * hp[i*32];
            }
        }
    }
    #pragma unroll
    for (int i = 0; i < 32; i++) {
        int f = i*32 + lane;
        float v = acc[i] + __ldg(&bias[f]);
        d_rst[(size_t)n*HF + f] = v > 0.f ? v : 0.f;
    }
}

// ---------------- bn1 stats ----------------
__global__ __launch_bounds__(256) void k_bn1stats() {
    int f = blockIdx.x * 256 + threadIdx.x;
    int n0 = blockIdx.y * 500;
    float s = 0.f, q = 0.f;
    for (int n = n0; n < n0 + 500; n++) {
        float v = d_rst[(size_t)n*HF + f];
        s += v; q += v*v;
    }
    atomicAdd(&d_bn1sum[f], s);
    atomicAdd(&d_bn1sum[1024 + f], q);
}

// ---------------- gated_conv2 (bn1 apply fused, bn2 stats) -------------------
// warp <-> co quad; lane = nl*4 + t2; f32x2 = co pair. ci = 128.
__global__ __launch_bounds__(256) void k_gated2(
    const float* __restrict__ w1, const float* __restrict__ b1,
    const float* __restrict__ w2, const float* __restrict__ b2,
    const float* __restrict__ w3, const float* __restrict__ b3,
    const float* __restrict__ bn1g, const float* __restrict__ bn1b)
{
    extern __shared__ __align__(16) float sm[];
    float* swc = sm;                     // 1152*36 = 41472
    float* ssc = sm + 41472;             // 1024
    float* ssh = sm + 42496;             // 1024
    float* sy  = sm + 43520;             // 8*1284 = 10272
    // total 53792 floats = 215168 B

    int tid = threadIdx.x;
    for (int i = tid; i < 12288; i += 256) {
        int co = i / 384, r = i % 384, ci = r / 3, k = r % 3;
        swc[(ci*9 + 0 + k)*WP + co] = w1[i];
        swc[(ci*9 + 3 + k)*WP + co] = w2[i];
        swc[(ci*9 + 6 + k)*WP + co] = w3[i];
    }
    float invN = 1.f/(float)NN;
    for (int f = tid; f < 1024; f += 256) {
        float mean = d_bn1sum[f]*invN;
        float var  = d_bn1sum[1024+f]*invN - mean*mean;
        float a = bn1g[f]*rsqrtf(var + BEPS);
        ssc[f] = a; ssh[f] = bn1b[f] - mean*a;
    }
    for (int i = tid; i < 1024; i += 256) {
        int nl = i >> 7, ci = i & 127;
        sy[nl*1284 + ci*10 + 0] = 0.f;
        sy[nl*1284 + ci*10 + 9] = 0.f;
    }
    __syncthreads();
    int node0 = blockIdx.x * 8;
    for (int i = tid; i < 8192; i += 256) {
        int nl = i >> 10, f = i & 1023;
        float v = d_rst[(size_t)(node0 + nl)*HF + f]*ssc[f] + ssh[f];
        int ci = f >> 3, t = f & 7;
        sy[nl*1284 + ci*10 + t + 1] = v;
    }
    __syncthreads();

    int w = tid >> 5, lane = tid & 31;
    int coq = w * 4;
    int nl = lane >> 2, t2 = lane & 3;
    const float* xb = &sy[nl*1284 + t2];

    ull acc[2][3][2];
    #pragma unroll
    for (int s = 0; s < 2; s++)
        #pragma unroll
        for (int pr = 0; pr < 2; pr++) {
            int c0 = coq + 2*pr;
            acc[s][0][pr] = pack2(b1[c0], b1[c0+1]);
            acc[s][1][pr] = pack2(b2[c0], b2[c0+1]);
            acc[s][2][pr] = pack2(b3[c0], b3[c0+1]);
        }

    #pragma unroll 2
    for (int ci = 0; ci < 128; ci++) {
        ull Xv[2][3];
        #pragma unroll
        for (int k = 0; k < 3; k++) {
            Xv[0][k] = dup2(xb[ci*10 + k]);
            Xv[1][k] = dup2(xb[ci*10 + 4 + k]);
        }
        #pragma unroll
        for (int j = 0; j < 3; j++)
            #pragma unroll
            for (int k = 0; k < 3; k++) {
                float4 W = *(const float4*)&swc[(ci*9 + j*3 + k)*WP + coq];
                ull w0, w1v; f4u2(W, w0, w1v);
                ffma2(acc[0][j][0], w0,  Xv[0][k]);
                ffma2(acc[0][j][1], w1v, Xv[0][k]);
                ffma2(acc[1][j][0], w0,  Xv[1][k]);
                ffma2(acc[1][j][1], w1v, Xv[1][k]);
            }
    }

    int n = node0 + nl;
    float gsum[4] = {0.f,0.f,0.f,0.f}, gsq[4] = {0.f,0.f,0.f,0.f};
    #pragma unroll
    for (int s = 0; s < 2; s++) {
        int t = t2 + 4*s;
        #pragma unroll
        for (int pr = 0; pr < 2; pr++) {
            float a10, a11, a20, a21, a30, a31;
            unpk2(acc[s][0][pr], a10, a11);
            unpk2(acc[s][1][pr], a20, a21);
            unpk2(acc[s][2][pr], a30, a31);
            int c0 = coq + 2*pr;
            float g0 = a10 * (1.f/(1.f + expf(-a20))) + a30; g0 = g0 > 0.f ? g0 : 0.f;
            float g1 = a11 * (1.f/(1.f + expf(-a21))) + a31; g1 = g1 > 0.f ? g1 : 0.f;
            d_xn[n*256 + c0*8 + t]     = g0;
            d_xn[n*256 + (c0+1)*8 + t] = g1;
            gsum[2*pr] += g0;   gsq[2*pr] += g0*g0;
            gsum[2*pr+1] += g1; gsq[2*pr+1] += g1*g1;
        }
    }
    __syncthreads();
    float* sred = sm;
    if (tid < 64) sred[tid] = 0.f;
    __syncthreads();
    #pragma unroll
    for (int q = 0; q < 4; q++) {
        atomicAdd(&sred[coq + q], gsum[q]);
        atomicAdd(&sred[32 + coq + q], gsq[q]);
    }
    __syncthreads();
    if (tid < 32) {
        atomicAdd(&d_bn2sum[tid],      sred[tid]);
        atomicAdd(&d_bn2sum[32 + tid], sred[32 + tid]);
    }
}

// ---------------- final ----------------
__global__ void k_out(float* __restrict__ out, const float* __restrict__ bn2g,
                      const float* __restrict__ bn2b) {
    __shared__ float ssc[32], ssh[32];
    int tid = threadIdx.x;
    if (tid < 32) {
        float inv = 1.f/(float)(NN*TT);
        float mean = d_bn2sum[tid]*inv;
        float var  = d_bn2sum[32+tid]*inv - mean*mean;
        float a = bn2g[tid]*rsqrtf(var + BEPS);
        ssc[tid] = a; ssh[tid] = bn2b[tid] - mean*a;
    }
    __syncthreads();
    int base = blockIdx.x * 2048;
    for (int o = tid; o < 2048; o += 256) {
        int i = base + o;
        if (i < NN*CT) {
            int c = (i >> 3) & 31;
            float v = d_xn[i]*ssc[c] + ssh[c] + d_res[i];
            out[i] = v > 0.f ? v : 0.f;
        }
    }
}

// ---------------- launch ----------------
extern "C" void kernel_launch(void* const* d_in, const int* in_sizes, int n_in,
                              void* d_out, int out_size) {
    const float* X      = (const float*)d_in[0];
    const int*   src    = (const int*)  d_in[1];
    const int*   dst    = (const int*)  d_in[2];
    const float* rp_w   = (const float*)d_in[3];
    const float* rp_b   = (const float*)d_in[4];
    const float* g1w1   = (const float*)d_in[5];
    const float* g1b1   = (const float*)d_in[6];
    const float* g1w2   = (const float*)d_in[7];
    const float* g1b2   = (const float*)d_in[8];
    const float* g1w3   = (const float*)d_in[9];
    const float* g1b3   = (const float*)d_in[10];
    const float* bn0g   = (const float*)d_in[11];
    const float* bn0b   = (const float*)d_in[12];
    const float* gatw   = (const float*)d_in[13];
    const float* attnl  = (const float*)d_in[14];
    const float* attnr  = (const float*)d_in[15];
    const float* gatb   = (const float*)d_in[16];
    const float* bn1g   = (const float*)d_in[17];
    const float* bn1b   = (const float*)d_in[18];
    const float* g2w1   = (const float*)d_in[19];
    const float* g2b1   = (const float*)d_in[20];
    const float* g2w2   = (const float*)d_in[21];
    const float* g2b2   = (const float*)d_in[22];
    const float* g2w3   = (const float*)d_in[23];
    const float* g2b3   = (const float*)d_in[24];
    const float* bn2g   = (const float*)d_in[25];
    const float* bn2b   = (const float*)d_in[26];
    float* out = (float*)d_out;

    static cudaStream_t s2 = 0;
    static cudaEvent_t evF = 0, evJ = 0;
    static int inited = 0;
    if (!inited) {
        cudaFuncSetAttribute(k_front,   cudaFuncAttributeMaxDynamicSharedMemorySize, 56448);
        cudaFuncSetAttribute(k_gemm_tc, cudaFuncAttributeMaxDynamicSharedMemorySize, 73728);
        cudaFuncSetAttribute(k_gated2,  cudaFuncAttributeMaxDynamicSharedMemorySize, 215168);
        cudaStreamCreateWithFlags(&s2, cudaStreamNonBlocking);
        cudaEventCreateWithFlags(&evF, cudaEventDisableTiming);
        cudaEventCreateWithFlags(&evJ, cudaEventDisableTiming);
        inited = 1;
    }

    void *p_b0, *p_b1, *p_b2, *p_cnt, *p_el, *p_er;
    cudaGetSymbolAddress(&p_b0, d_bn0sum);
    cudaGetSymbolAddress(&p_b1, d_bn1sum);
    cudaGetSymbolAddress(&p_b2, d_bn2sum);
    cudaGetSymbolAddress(&p_cnt, d_counts);
    cudaGetSymbolAddress(&p_el, d_el);
    cudaGetSymbolAddress(&p_er, d_er);

    cudaMemsetAsync(p_b0, 0, 64*sizeof(float));
    cudaMemsetAsync(p_b1, 0, 2048*sizeof(float));
    cudaMemsetAsync(p_b2, 0, 64*sizeof(float));
    cudaMemsetAsync(p_el, 0, NN*HH*sizeof(float));
    cudaMemsetAsync(p_er, 0, NN*HH*sizeof(float));

    // fork: CSR build on s2, overlapped with front/pack/GEMM
    cudaEventRecord(evF, 0);
    cudaStreamWaitEvent(s2, evF, 0);
    cudaMemsetAsync(p_cnt, 0, NN*sizeof(int), s2);
    k_count<<<(EE + 255)/256, 256, 0, s2>>>(dst);
    k_scan<<<1, 1024, 0, s2>>>();
    k_fill<<<(EE + 255)/256, 256, 0, s2>>>(src, dst);
    cudaEventRecord(evJ, s2);

    k_front<<<NN/8, 256, 56448>>>(X, rp_w, rp_b, g1w1, g1b1, g1w2, g1b2, g1w3, g1b3);
    k_packB<<<(HF*256 + 255)/256, 256>>>(gatw);
    k_packA<<<(NN*CT + 16383)/16384, 256>>>(bn0g, bn0b);
    k_gemm_tc<<<dim3(MPAD/128, HF/128), 256, 73728>>>(attnl, attnr);

    cudaStreamWaitEvent(0, evJ, 0);
    k_agg<<<(NN*32 + 255)/256, 256>>>(gatb);
    k_bn1stats<<<dim3(4, 40), 256>>>();
    k_gated2<<<NN/8, 256, 215168>>>(g2w1, g2b1, g2w2, g2b2, g2w3, g2b3, bn1g, bn1b);
    k_out<<<(NN*CT + 2047)/2048, 256>>>(out, bn2g, bn2b);
}